// round 5
// baseline (speedup 1.0000x reference)
#include <cuda_runtime.h>
#include <math.h>
#include <stdint.h>

// LSTM cell B=4096, IN=H=1024 — int8 Ozaki-split GEMM, IMMA m16n8k32 tensor
// warps (rows 0-127 of each 144-row tile) + dp4a ALU warps (rows 128-143)
// co-issuing from the same smem tiles.
//   hx[m,k] ≈ sa_m/16256 · (128·A1 + A2),  W col n: sb_n/16256 · (128·B1 + B2)
//   pre = sa·sb/16256^2 · (16384·A1B1 + 128·(A1B2 + A2B1))   (A2B2 dropped)
// K''=6144: ktiles 0-15 A1·B1, then acc<<=7, 16-31 A2·B1, 32-47 A1·B2.

#define BM 144                          // 128 tensor rows + 16 dp4a rows
#define BN 256
#define KTILES 48
#define STAGES 3
#define THREADS 384
#define A_STAGE_BYTES (BM * 128)        // 18432
#define B_STAGE_BYTES (BN * 128)        // 32768
#define STAGE_BYTES (A_STAGE_BYTES + B_STAGE_BYTES)
#define SMEM_DYN (STAGES * STAGE_BYTES) // 153600

static __device__ __align__(16) int8_t g_Aq[4096ull * 4096];  // [m][A1|A2]
static __device__ __align__(16) int8_t g_Bq[4096ull * 4096];  // [n=g*1024+c][B1|B2]
static __device__ float g_sa[4096];
static __device__ float g_sb[4096];     // sb_n * 128 / 16256^2
static __device__ float g_pre[4ull * 4096ull * 1024ull];

// ---------------- PTX helpers (baseline ISA) ----------------
__device__ __forceinline__ uint32_t smem_u32(const void* p) {
    return (uint32_t)__cvta_generic_to_shared(p);
}
__device__ __forceinline__ void cp16(uint32_t dst, const void* src) {
    asm volatile("cp.async.cg.shared.global [%0], [%1], 16;\n" :: "r"(dst), "l"(src));
}
__device__ __forceinline__ void cp_commit() {
    asm volatile("cp.async.commit_group;\n" ::: "memory");
}
#define CP_WAIT(N) asm volatile("cp.async.wait_group %0;\n" :: "n"(N) : "memory")

__device__ __forceinline__ void ldsm_x4(uint32_t* r, uint32_t addr) {
    asm volatile("ldmatrix.sync.aligned.m8n8.x4.shared.b16 {%0,%1,%2,%3}, [%4];\n"
                 : "=r"(r[0]), "=r"(r[1]), "=r"(r[2]), "=r"(r[3]) : "r"(addr));
}
__device__ __forceinline__ void lds128(int* v, uint32_t addr) {
    asm volatile("ld.shared.v4.b32 {%0,%1,%2,%3}, [%4];\n"
                 : "=r"(v[0]), "=r"(v[1]), "=r"(v[2]), "=r"(v[3]) : "r"(addr));
}
__device__ __forceinline__ void imma16832(int* c, const uint32_t* a,
                                          uint32_t b0, uint32_t b1) {
    asm volatile(
        "mma.sync.aligned.m16n8k32.row.col.s32.s8.s8.s32 "
        "{%0,%1,%2,%3}, {%4,%5,%6,%7}, {%8,%9}, {%0,%1,%2,%3};\n"
        : "+r"(c[0]), "+r"(c[1]), "+r"(c[2]), "+r"(c[3])
        : "r"(a[0]), "r"(a[1]), "r"(a[2]), "r"(a[3]), "r"(b0), "r"(b1));
}

// ---------------- quantization ----------------
__global__ __launch_bounds__(256)
void quant_hx(const float* __restrict__ x, const float* __restrict__ h) {
    __shared__ float sred[256];
    const int m = blockIdx.x;
    const int t = threadIdx.x;
    const float* src = (t < 128) ? (x + (size_t)m * 1024 + t * 8)
                                 : (h + (size_t)m * 1024 + (t - 128) * 8);
    float4 v0 = *(const float4*)src;
    float4 v1 = *(const float4*)(src + 4);
    float vals[8] = {v0.x, v0.y, v0.z, v0.w, v1.x, v1.y, v1.z, v1.w};
    float mx = 0.0f;
    #pragma unroll
    for (int j = 0; j < 8; ++j) mx = fmaxf(mx, fabsf(vals[j]));
    sred[t] = mx;
    __syncthreads();
    for (int s = 128; s > 0; s >>= 1) {
        if (t < s) sred[t] = fmaxf(sred[t], sred[t + s]);
        __syncthreads();
    }
    const float sa = fmaxf(sred[0], 1e-30f);
    if (t == 0) g_sa[m] = sa;
    const float inv = 16256.0f / sa;
    char d1[8], d2[8];
    #pragma unroll
    for (int j = 0; j < 8; ++j) {
        int vi = __float2int_rn(vals[j] * inv);
        int b1 = (vi + 64) >> 7;
        int b2 = vi - (b1 << 7);
        d1[j] = (char)b1;
        d2[j] = (char)b2;
    }
    size_t base = (size_t)m * 4096 + t * 8;
    *(uint2*)&g_Aq[base]        = *(uint2*)d1;
    *(uint2*)&g_Aq[base + 2048] = *(uint2*)d2;
}

__global__ __launch_bounds__(256)
void quant_w(const float* __restrict__ Wf, const float* __restrict__ Wi,
             const float* __restrict__ Ws, const float* __restrict__ Wp) {
    __shared__ float red[8][32];
    __shared__ float smax[32];
    __shared__ __align__(8) char t1[32][64];
    __shared__ __align__(8) char t2[32][64];

    const int g = blockIdx.y;
    const float* __restrict__ W = (g == 0) ? Wf : (g == 1) ? Wi : (g == 2) ? Ws : Wp;
    const int n0 = blockIdx.x * 32;
    const int tx = threadIdx.x & 31;
    const int tk = threadIdx.x >> 5;   // 0..7

    float mx = 0.0f;
    for (int k = tk; k < 2048; k += 8)
        mx = fmaxf(mx, fabsf(W[(size_t)k * 1024 + n0 + tx]));
    red[tk][tx] = mx;
    __syncthreads();
    if (tk == 0) {
        float m = red[0][tx];
        #pragma unroll
        for (int j = 1; j < 8; ++j) m = fmaxf(m, red[j][tx]);
        m = fmaxf(m, 1e-30f);
        smax[tx] = m;
        g_sb[g * 1024 + n0 + tx] = m * (128.0f / (16256.0f * 16256.0f));
    }
    __syncthreads();
    const float inv = 16256.0f / smax[tx];

    for (int kt = 0; kt < 2048; kt += 64) {
        #pragma unroll
        for (int j = 0; j < 8; ++j) {
            int k = kt + tk * 8 + j;
            float v = W[(size_t)k * 1024 + n0 + tx] * inv;
            int vi = __float2int_rn(v);
            int b1 = (vi + 64) >> 7;
            int b2 = vi - (b1 << 7);
            t1[tx][tk * 8 + j] = (char)b1;
            t2[tx][tk * 8 + j] = (char)b2;
        }
        __syncthreads();
        const int r = threadIdx.x >> 3, seg = threadIdx.x & 7;
        size_t row = (size_t)(g * 1024 + n0 + r) * 4096;
        *(uint2*)&g_Bq[row + kt + seg * 8]        = *(uint2*)&t1[r][seg * 8];
        *(uint2*)&g_Bq[row + 2048 + kt + seg * 8] = *(uint2*)&t2[r][seg * 8];
        __syncthreads();
    }
}

// ---------------- hybrid GEMM ----------------
__device__ __forceinline__ void koffs(int kt, int& ka, int& kb) {
    if (kt < 16)      { ka = kt << 7;                 kb = kt << 7; }
    else if (kt < 32) { ka = 2048 + ((kt - 16) << 7); kb = (kt - 16) << 7; }
    else              { ka = (kt - 32) << 7;          kb = 2048 + ((kt - 32) << 7); }
}

__device__ __forceinline__ void load_stage(uint32_t sbase, int stage, int m0, int n0,
                                           int tid) {
    const uint32_t sb = sbase + (uint32_t)(stage % STAGES) * STAGE_BYTES;
    int ka, kb;
    koffs(stage, ka, kb);
    #pragma unroll
    for (int j = 0; j < 3; ++j) {              // A: 144 rows x 128B = 1152 cp16
        int id = j * THREADS + tid;
        int r = id >> 3, c = id & 7;
        int gr = m0 + r; if (gr > 4095) gr = 4095;
        uint32_t dst = sb + (uint32_t)(r * 128 + ((c ^ (r & 7)) * 16));
        cp16(dst, g_Aq + ((size_t)gr * 4096 + ka + c * 16));
    }
    #pragma unroll
    for (int j = 0; j < 6; ++j) {              // B: 256 rows x 128B = 2048 cp16
        int id = j * THREADS + tid;
        if (id < 2048) {
            int r = id >> 3, c = id & 7;
            uint32_t dst = sb + (uint32_t)A_STAGE_BYTES
                         + (uint32_t)(r * 128 + ((c ^ (r & 7)) * 16));
            cp16(dst, g_Bq + ((size_t)(n0 + r) * 4096 + kb + c * 16));
        }
    }
}

__global__ __launch_bounds__(THREADS, 1)
void gemm_hybrid() {
    extern __shared__ char dyn[];
    const uint32_t sbase = smem_u32(dyn);

    const int tid = threadIdx.x;
    const int wid = tid >> 5;
    const int lane = tid & 31;
    const int m0 = blockIdx.y * BM;
    const int n0 = blockIdx.x * BN;

    // tensor-warp geometry (wid 0..7)
    const int warp_m = wid & 1;
    const int warp_n = wid >> 1;
    const int lrow = lane & 15;
    const int lhi  = lane >> 4;
    // dp4a-warp geometry (wid 8..11)
    const int dt = tid - 256;                  // 0..127
    const int rr = (dt >> 3) & 15;             // 0..15 (masked for tensor thr)
    const int cg = dt & 7;                     // 0..7 -> 32-col group

    // acc[0..127]: tensor accums; dp4a warps alias acc[96..127] (32 cols).
    int acc[128];
    #pragma unroll
    for (int i = 0; i < 128; ++i) acc[i] = 0;

    load_stage(sbase, 0, m0, n0, tid); cp_commit();
    load_stage(sbase, 1, m0, n0, tid); cp_commit();

    for (int kt = 0; kt < KTILES; ++kt) {
        CP_WAIT(1);
        __syncthreads();

        if (kt + 2 < KTILES) load_stage(sbase, kt + 2, m0, n0, tid);
        cp_commit();

        if (kt == 16) {                 // acc = 128*G1; continue with cross terms
            #pragma unroll
            for (int i = 0; i < 128; ++i) acc[i] <<= 7;
        }

        const uint32_t sA = sbase + (uint32_t)(kt % STAGES) * STAGE_BYTES;
        const uint32_t sB = sA + A_STAGE_BYTES;

        if (wid < 8) {
            // ---- tensor warps: rows 0..127 ----
            #pragma unroll
            for (int ks = 0; ks < 4; ++ks) {
                const int kc = ks * 2 + lhi;
                uint32_t a[4][4];
                #pragma unroll
                for (int mi = 0; mi < 4; ++mi) {
                    int r = warp_m * 64 + mi * 16 + lrow;
                    ldsm_x4(a[mi], sA + (uint32_t)(r * 128 + ((kc ^ (r & 7)) * 16)));
                }
                #pragma unroll
                for (int nj = 0; nj < 4; ++nj) {
                    uint32_t b[4];
                    int r = warp_n * 64 + nj * 16 + lrow;
                    ldsm_x4(b, sB + (uint32_t)(r * 128 + ((kc ^ (r & 7)) * 16)));
                    #pragma unroll
                    for (int mi = 0; mi < 4; ++mi) {
                        imma16832(&acc[(mi * 8 + 2 * nj) * 4],     a[mi], b[0], b[2]);
                        imma16832(&acc[(mi * 8 + 2 * nj + 1) * 4], a[mi], b[1], b[3]);
                    }
                }
            }
        } else {
            // ---- dp4a warps: rows 128..143, cols cg*32 + rot(cc) ----
            const uint32_t aRow = sA + (uint32_t)((128 + rr) * 128);
            #pragma unroll
            for (int c8 = 0; c8 < 8; ++c8) {
                int a4[4];
                lds128(a4, aRow + (uint32_t)((c8 ^ (rr & 7)) << 4));
                #pragma unroll
                for (int cc = 0; cc < 32; ++cc) {
                    int r2 = cg * 32 + ((cc + cg) & 31);
                    int b4[4];
                    lds128(b4, sB + (uint32_t)(r2 * 128 + ((c8 ^ (r2 & 7)) << 4)));
                    int s = acc[96 + cc];
                    s = __dp4a(a4[0], b4[0], s);
                    s = __dp4a(a4[1], b4[1], s);
                    s = __dp4a(a4[2], b4[2], s);
                    s = __dp4a(a4[3], b4[3], s);
                    acc[96 + cc] = s;
                }
            }
        }
    }

    // ---------------- epilogue ----------------
    const int gate = n0 >> 10;                 // 256 | 1024 -> single gate/CTA
    float* __restrict__ outg = g_pre + (size_t)gate * (4096ull * 1024ull);

    if (wid < 8) {
        const int gid = lane >> 2, tig = lane & 3;
        const int col0 = (n0 & 1023) + warp_n * 64;
        const int ngb = n0 + warp_n * 64;
        #pragma unroll
        for (int mi = 0; mi < 4; ++mi) {
            int row = m0 + warp_m * 64 + mi * 16 + gid;
            float s0 = g_sa[row < 4096 ? row : 4095];
            float s1 = g_sa[row + 8 < 4096 ? row + 8 : 4095];
            float* p0 = outg + (size_t)row * 1024 + col0;
            float* p1 = p0 + 8ull * 1024ull;
            #pragma unroll
            for (int nj = 0; nj < 8; ++nj) {
                int col = nj * 8 + tig * 2;
                float2 sb2 = *(const float2*)&g_sb[ngb + col];
                int* ac = &acc[(mi * 8 + nj) * 4];
                if (row < 4096)
                    *(float2*)(p0 + col) = make_float2(s0 * sb2.x * (float)ac[0],
                                                       s0 * sb2.y * (float)ac[1]);
                if (row + 8 < 4096)
                    *(float2*)(p1 + col) = make_float2(s1 * sb2.x * (float)ac[2],
                                                       s1 * sb2.y * (float)ac[3]);
            }
        }
    } else {
        const int row = m0 + 128 + rr;
        if (row < 4096) {
            const float s0 = g_sa[row];
            float* p = outg + (size_t)row * 1024 + (n0 & 1023);
            #pragma unroll
            for (int cc = 0; cc < 32; ++cc) {
                int cl = cg * 32 + ((cc + cg) & 31);
                p[cl] = s0 * g_sb[n0 + cl] * (float)acc[96 + cc];
            }
        }
    }
}

// ---------------- fused eltwise ----------------
__device__ __forceinline__ float sigf(float z) { return 1.0f / (1.0f + expf(-z)); }

__global__ __launch_bounds__(256)
void lstm_eltwise_kernel(const float* __restrict__ c,
                         const float* __restrict__ bf, const float* __restrict__ bi,
                         const float* __restrict__ bs, const float* __restrict__ bp,
                         float* __restrict__ out) {
    const size_t G = 4096ull * 1024ull;
    const size_t i4 = (size_t)blockIdx.x * blockDim.x + threadIdx.x;
    const size_t idx = i4 * 4;
    const int col = (int)(idx & 1023);

    float4 pf = *(const float4*)&g_pre[idx];
    float4 pi = *(const float4*)&g_pre[G + idx];
    float4 ps = *(const float4*)&g_pre[2 * G + idx];
    float4 pp = *(const float4*)&g_pre[3 * G + idx];
    float4 vbf = *(const float4*)&bf[col];
    float4 vbi = *(const float4*)&bi[col];
    float4 vbs = *(const float4*)&bs[col];
    float4 vbp = *(const float4*)&bp[col];
    float4 vc  = *(const float4*)&c[idx];

    const float* pfv = (const float*)&pf;  const float* piv = (const float*)&pi;
    const float* psv = (const float*)&ps;  const float* ppv = (const float*)&pp;
    const float* bfv = (const float*)&vbf; const float* biv = (const float*)&vbi;
    const float* bsv = (const float*)&vbs; const float* bpv = (const float*)&vbp;
    const float* cv  = (const float*)&vc;

    float4 o; float* ov = (float*)&o;
    #pragma unroll
    for (int j = 0; j < 4; ++j) {
        float f = sigf(pfv[j] + bfv[j]);
        float i = sigf(piv[j] + biv[j]);
        float s = sigf(psv[j] + bsv[j]);
        float p = tanhf(ppv[j] + bpv[j]);
        float cn = cv[j] * f + i * p;
        ov[j] = tanhf(cn) * s;
    }
    *(float4*)&out[idx] = o;
}

// ---------------- launch ----------------
extern "C" void kernel_launch(void* const* d_in, const int* in_sizes, int n_in,
                              void* d_out, int out_size) {
    const float* x  = (const float*)d_in[0];
    const float* h  = (const float*)d_in[1];
    const float* c  = (const float*)d_in[2];
    const float* Wf = (const float*)d_in[3];
    const float* bf = (const float*)d_in[4];
    const float* Wi = (const float*)d_in[5];
    const float* bi = (const float*)d_in[6];
    const float* Ws = (const float*)d_in[7];
    const float* bs = (const float*)d_in[8];
    const float* Wp = (const float*)d_in[9];
    const float* bp = (const float*)d_in[10];
    float* out = (float*)d_out;

    cudaFuncSetAttribute(gemm_hybrid, cudaFuncAttributeMaxDynamicSharedMemorySize,
                         SMEM_DYN);

    quant_hx<<<4096, 256>>>(x, h);
    quant_w<<<dim3(32, 4), 256>>>(Wf, Wi, Ws, Wp);
    gemm_hybrid<<<dim3(4096 / BN, (4096 + BM - 1) / BM), THREADS, SMEM_DYN>>>();
    lstm_eltwise_kernel<<<4096, 256>>>(c, bf, bi, bs, bp, out);
}

// round 6
// speedup vs baseline: 3.0627x; 3.0627x over previous
#include <cuda_runtime.h>
#include <math.h>
#include <stdint.h>

// LSTM cell B=4096, IN=H=1024 — int8 Ozaki-split GEMM on IMMA m16n8k32.
//   hx[m,k] ≈ sa_m/16256 · (128·A1 + A2),  W col n: sb_n/16256 · (128·B1 + B2)
//   pre = sa·sb/16256^2 · (16384·A1B1 + 128·(A1B2 + A2B1))   (A2B2 dropped)
// K''=6144: ktiles 0-15 A1·B1, then acc<<=7, 16-31 A2·B1, 32-47 A1·B2.
// R6: R4 GEMM restored; weight quant parallelized (atomicMax colmax pass +
// 4096-block quant pass) to remove the 128-block latency-bound straggler.

#define BM 128
#define BN 256
#define KTILES 48
#define STAGES 3
#define A_STAGE_BYTES (BM * 128)        // 16384
#define B_STAGE_BYTES (BN * 128)        // 32768
#define STAGE_BYTES (A_STAGE_BYTES + B_STAGE_BYTES)
#define SMEM_DYN (STAGES * STAGE_BYTES)

#define SBSCALE (128.0f / (16256.0f * 16256.0f))

static __device__ __align__(16) int8_t g_Aq[4096ull * 4096];  // [m][A1|A2]
static __device__ __align__(16) int8_t g_Bq[4096ull * 4096];  // [n=g*1024+c][B1|B2]
static __device__ float g_sa[4096];          // row max (raw)
static __device__ unsigned g_cmax[4096];     // col max |W| as float bits (atomicMax)
static __device__ float g_pre[4ull * 4096ull * 1024ull];

// ---------------- PTX helpers (baseline sm_80 ISA) ----------------
__device__ __forceinline__ uint32_t smem_u32(const void* p) {
    return (uint32_t)__cvta_generic_to_shared(p);
}
__device__ __forceinline__ void cp16(uint32_t dst, const void* src) {
    asm volatile("cp.async.cg.shared.global [%0], [%1], 16;\n" :: "r"(dst), "l"(src));
}
__device__ __forceinline__ void cp_commit() {
    asm volatile("cp.async.commit_group;\n" ::: "memory");
}
#define CP_WAIT(N) asm volatile("cp.async.wait_group %0;\n" :: "n"(N) : "memory")

__device__ __forceinline__ void ldsm_x4(uint32_t* r, uint32_t addr) {
    asm volatile("ldmatrix.sync.aligned.m8n8.x4.shared.b16 {%0,%1,%2,%3}, [%4];\n"
                 : "=r"(r[0]), "=r"(r[1]), "=r"(r[2]), "=r"(r[3]) : "r"(addr));
}
__device__ __forceinline__ void imma16832(int* c, const uint32_t* a,
                                          uint32_t b0, uint32_t b1) {
    asm volatile(
        "mma.sync.aligned.m16n8k32.row.col.s32.s8.s8.s32 "
        "{%0,%1,%2,%3}, {%4,%5,%6,%7}, {%8,%9}, {%0,%1,%2,%3};\n"
        : "+r"(c[0]), "+r"(c[1]), "+r"(c[2]), "+r"(c[3])
        : "r"(a[0]), "r"(a[1]), "r"(a[2]), "r"(a[3]), "r"(b0), "r"(b1));
}

// ---------------- activation quantization ----------------
__global__ __launch_bounds__(256)
void quant_hx(const float* __restrict__ x, const float* __restrict__ h) {
    __shared__ float sred[256];
    const int m = blockIdx.x;
    const int t = threadIdx.x;
    const float* src = (t < 128) ? (x + (size_t)m * 1024 + t * 8)
                                 : (h + (size_t)m * 1024 + (t - 128) * 8);
    float4 v0 = *(const float4*)src;
    float4 v1 = *(const float4*)(src + 4);
    float vals[8] = {v0.x, v0.y, v0.z, v0.w, v1.x, v1.y, v1.z, v1.w};
    float mx = 0.0f;
    #pragma unroll
    for (int j = 0; j < 8; ++j) mx = fmaxf(mx, fabsf(vals[j]));
    sred[t] = mx;
    __syncthreads();
    for (int s = 128; s > 0; s >>= 1) {
        if (t < s) sred[t] = fmaxf(sred[t], sred[t + s]);
        __syncthreads();
    }
    const float sa = fmaxf(sred[0], 1e-30f);
    if (t == 0) g_sa[m] = sa;
    const float inv = 16256.0f / sa;
    char d1[8], d2[8];
    #pragma unroll
    for (int j = 0; j < 8; ++j) {
        int vi = __float2int_rn(vals[j] * inv);
        int b1 = (vi + 64) >> 7;
        int b2 = vi - (b1 << 7);
        d1[j] = (char)b1;
        d2[j] = (char)b2;
    }
    size_t base = (size_t)m * 4096 + t * 8;
    *(uint2*)&g_Aq[base]        = *(uint2*)d1;
    *(uint2*)&g_Aq[base + 2048] = *(uint2*)d2;
}

// ---------------- weight quantization (2-pass, parallel) ----------------
// Pass 1: per-column |max| via block-reduce + atomicMax on float bits.
// Positive floats compare correctly as ints; atomicMax is idempotent, so
// repeated graph replays recompute the identical value (deterministic).
__global__ __launch_bounds__(256)
void colmax_w(const float* __restrict__ Wf, const float* __restrict__ Wi,
              const float* __restrict__ Ws, const float* __restrict__ Wp) {
    __shared__ float red[8][33];
    const int g = blockIdx.z;
    const float* __restrict__ W = (g == 0) ? Wf : (g == 1) ? Wi : (g == 2) ? Ws : Wp;
    const int n0 = blockIdx.x * 32;
    const int k0 = blockIdx.y * 256;
    const int tx = threadIdx.x & 31;
    const int tk = threadIdx.x >> 5;   // 0..7

    float mx = 0.0f;
    #pragma unroll 8
    for (int i = 0; i < 32; ++i) {
        int k = k0 + tk + i * 8;
        mx = fmaxf(mx, fabsf(W[(size_t)k * 1024 + n0 + tx]));
    }
    red[tk][tx] = mx;
    __syncthreads();
    if (tk == 0) {
        float m = red[0][tx];
        #pragma unroll
        for (int j = 1; j < 8; ++j) m = fmaxf(m, red[j][tx]);
        atomicMax((int*)&g_cmax[g * 1024 + n0 + tx], __float_as_int(m));
    }
}

// Pass 2: quantize 32 cols x 64 k per block (4096 blocks), smem transpose.
__global__ __launch_bounds__(256)
void quant_w2(const float* __restrict__ Wf, const float* __restrict__ Wi,
              const float* __restrict__ Ws, const float* __restrict__ Wp) {
    __shared__ __align__(8) char t1[32][64];
    __shared__ __align__(8) char t2[32][64];
    const int g = blockIdx.z;
    const float* __restrict__ W = (g == 0) ? Wf : (g == 1) ? Wi : (g == 2) ? Ws : Wp;
    const int n0 = blockIdx.x * 32;
    const int kt = blockIdx.y * 64;
    const int tx = threadIdx.x & 31;
    const int tk = threadIdx.x >> 5;   // 0..7

    const float cm = fmaxf(__int_as_float((int)g_cmax[g * 1024 + n0 + tx]), 1e-30f);
    const float inv = 16256.0f / cm;

    #pragma unroll
    for (int j = 0; j < 8; ++j) {
        int k = kt + tk * 8 + j;
        float v = W[(size_t)k * 1024 + n0 + tx] * inv;
        int vi = __float2int_rn(v);
        int b1 = (vi + 64) >> 7;
        int b2 = vi - (b1 << 7);
        t1[tx][tk * 8 + j] = (char)b1;
        t2[tx][tk * 8 + j] = (char)b2;
    }
    __syncthreads();
    const int r = threadIdx.x >> 3, seg = threadIdx.x & 7;
    size_t row = (size_t)(g * 1024 + n0 + r) * 4096;
    *(uint2*)&g_Bq[row + kt + seg * 8]        = *(uint2*)&t1[r][seg * 8];
    *(uint2*)&g_Bq[row + 2048 + kt + seg * 8] = *(uint2*)&t2[r][seg * 8];
}

// ---------------- IMMA GEMM (R4-proven) ----------------
__device__ __forceinline__ void koffs(int kt, int& ka, int& kb) {
    if (kt < 16)      { ka = kt << 7;                 kb = kt << 7; }
    else if (kt < 32) { ka = 2048 + ((kt - 16) << 7); kb = (kt - 16) << 7; }
    else              { ka = (kt - 32) << 7;          kb = 2048 + ((kt - 32) << 7); }
}

__device__ __forceinline__ void load_stage(uint32_t sbase, int stage, int m0, int n0,
                                           int tid) {
    const uint32_t sb = sbase + (uint32_t)(stage % STAGES) * STAGE_BYTES;
    int ka, kb;
    koffs(stage, ka, kb);
    #pragma unroll
    for (int j = 0; j < 4; ++j) {              // A: 128 rows x 128B
        int id = j * 256 + tid;
        int r = id >> 3, c = id & 7;
        uint32_t dst = sb + (uint32_t)(r * 128 + ((c ^ (r & 7)) * 16));
        cp16(dst, g_Aq + ((size_t)(m0 + r) * 4096 + ka + c * 16));
    }
    #pragma unroll
    for (int j = 0; j < 8; ++j) {              // B: 256 rows x 128B
        int id = j * 256 + tid;
        int r = id >> 3, c = id & 7;
        uint32_t dst = sb + (uint32_t)A_STAGE_BYTES
                     + (uint32_t)(r * 128 + ((c ^ (r & 7)) * 16));
        cp16(dst, g_Bq + ((size_t)(n0 + r) * 4096 + kb + c * 16));
    }
}

__global__ __launch_bounds__(256, 1)
void gemm_imma() {
    extern __shared__ char dyn[];
    const uint32_t sbase = smem_u32(dyn);

    const int tid = threadIdx.x;
    const int wid = tid >> 5;
    const int lane = tid & 31;
    const int warp_m = wid & 1;
    const int warp_n = wid >> 1;
    const int m0 = blockIdx.y * BM;
    const int n0 = blockIdx.x * BN;

    const int lrow = lane & 15;
    const int lhi  = lane >> 4;

    int acc[4][8][4];
    #pragma unroll
    for (int mi = 0; mi < 4; ++mi)
        #pragma unroll
        for (int nj = 0; nj < 8; ++nj)
            #pragma unroll
            for (int q = 0; q < 4; ++q) acc[mi][nj][q] = 0;

    load_stage(sbase, 0, m0, n0, tid); cp_commit();
    load_stage(sbase, 1, m0, n0, tid); cp_commit();

    for (int kt = 0; kt < KTILES; ++kt) {
        CP_WAIT(1);
        __syncthreads();

        if (kt + 2 < KTILES) load_stage(sbase, kt + 2, m0, n0, tid);
        cp_commit();

        if (kt == 16) {                 // acc = 128*G1; continue with cross terms
            #pragma unroll
            for (int mi = 0; mi < 4; ++mi)
                #pragma unroll
                for (int nj = 0; nj < 8; ++nj)
                    #pragma unroll
                    for (int q = 0; q < 4; ++q) acc[mi][nj][q] <<= 7;
        }

        const uint32_t sA = sbase + (uint32_t)(kt % STAGES) * STAGE_BYTES;
        const uint32_t sB = sA + A_STAGE_BYTES;

        #pragma unroll
        for (int ks = 0; ks < 4; ++ks) {       // 4 x k32 per 128B stage
            const int kc = ks * 2 + lhi;       // 16B chunk 0..7
            uint32_t a[4][4], b[4][4];
            #pragma unroll
            for (int mi = 0; mi < 4; ++mi) {
                int r = warp_m * 64 + mi * 16 + lrow;
                uint32_t addr = sA + (uint32_t)(r * 128 + ((kc ^ (r & 7)) * 16));
                ldsm_x4(a[mi], addr);
            }
            #pragma unroll
            for (int nj = 0; nj < 4; ++nj) {
                int r = warp_n * 64 + nj * 16 + lrow;
                uint32_t addr = sB + (uint32_t)(r * 128 + ((kc ^ (r & 7)) * 16));
                ldsm_x4(b[nj], addr);
            }
            #pragma unroll
            for (int mi = 0; mi < 4; ++mi)
                #pragma unroll
                for (int nj = 0; nj < 4; ++nj) {
                    imma16832(acc[mi][2 * nj],     a[mi], b[nj][0], b[nj][2]);
                    imma16832(acc[mi][2 * nj + 1], a[mi], b[nj][1], b[nj][3]);
                }
        }
    }

    // Epilogue: pre = g_sa[row] * (colmax[n]*SBSCALE) * acc
    const int gid = lane >> 2, tig = lane & 3;
    const int ngb = n0 + warp_n * 64;          // global col 0..4095
    const int gate = ngb >> 10;
    const int col0 = ngb & 1023;
    float* __restrict__ outg = g_pre + (size_t)gate * (4096ull * 1024ull);
    const float* __restrict__ cmf = (const float*)g_cmax;
    #pragma unroll
    for (int mi = 0; mi < 4; ++mi) {
        int row = m0 + warp_m * 64 + mi * 16 + gid;
        float s0 = g_sa[row] * SBSCALE;
        float s1 = g_sa[row + 8] * SBSCALE;
        float* p0 = outg + (size_t)row * 1024 + col0;
        float* p1 = p0 + 8ull * 1024ull;
        #pragma unroll
        for (int nj = 0; nj < 8; ++nj) {
            int col = nj * 8 + tig * 2;
            float2 sb2 = *(const float2*)&cmf[ngb + col];
            *(float2*)(p0 + col) = make_float2(s0 * sb2.x * (float)acc[mi][nj][0],
                                               s0 * sb2.y * (float)acc[mi][nj][1]);
            *(float2*)(p1 + col) = make_float2(s1 * sb2.x * (float)acc[mi][nj][2],
                                               s1 * sb2.y * (float)acc[mi][nj][3]);
        }
    }
}

// ---------------- fused eltwise ----------------
__device__ __forceinline__ float sigf(float z) { return 1.0f / (1.0f + expf(-z)); }

__global__ __launch_bounds__(256)
void lstm_eltwise_kernel(const float* __restrict__ c,
                         const float* __restrict__ bf, const float* __restrict__ bi,
                         const float* __restrict__ bs, const float* __restrict__ bp,
                         float* __restrict__ out) {
    const size_t G = 4096ull * 1024ull;
    const size_t i4 = (size_t)blockIdx.x * blockDim.x + threadIdx.x;
    const size_t idx = i4 * 4;
    const int col = (int)(idx & 1023);

    float4 pf = *(const float4*)&g_pre[idx];
    float4 pi = *(const float4*)&g_pre[G + idx];
    float4 ps = *(const float4*)&g_pre[2 * G + idx];
    float4 pp = *(const float4*)&g_pre[3 * G + idx];
    float4 vbf = *(const float4*)&bf[col];
    float4 vbi = *(const float4*)&bi[col];
    float4 vbs = *(const float4*)&bs[col];
    float4 vbp = *(const float4*)&bp[col];
    float4 vc  = *(const float4*)&c[idx];

    const float* pfv = (const float*)&pf;  const float* piv = (const float*)&pi;
    const float* psv = (const float*)&ps;  const float* ppv = (const float*)&pp;
    const float* bfv = (const float*)&vbf; const float* biv = (const float*)&vbi;
    const float* bsv = (const float*)&vbs; const float* bpv = (const float*)&vbp;
    const float* cv  = (const float*)&vc;

    float4 o; float* ov = (float*)&o;
    #pragma unroll
    for (int j = 0; j < 4; ++j) {
        float f = sigf(pfv[j] + bfv[j]);
        float i = sigf(piv[j] + biv[j]);
        float s = sigf(psv[j] + bsv[j]);
        float p = tanhf(ppv[j] + bpv[j]);
        float cn = cv[j] * f + i * p;
        ov[j] = tanhf(cn) * s;
    }
    *(float4*)&out[idx] = o;
}

// ---------------- launch ----------------
extern "C" void kernel_launch(void* const* d_in, const int* in_sizes, int n_in,
                              void* d_out, int out_size) {
    const float* x  = (const float*)d_in[0];
    const float* h  = (const float*)d_in[1];
    const float* c  = (const float*)d_in[2];
    const float* Wf = (const float*)d_in[3];
    const float* bf = (const float*)d_in[4];
    const float* Wi = (const float*)d_in[5];
    const float* bi = (const float*)d_in[6];
    const float* Ws = (const float*)d_in[7];
    const float* bs = (const float*)d_in[8];
    const float* Wp = (const float*)d_in[9];
    const float* bp = (const float*)d_in[10];
    float* out = (float*)d_out;

    cudaFuncSetAttribute(gemm_imma, cudaFuncAttributeMaxDynamicSharedMemorySize,
                         SMEM_DYN);

    quant_hx<<<4096, 256>>>(x, h);
    colmax_w<<<dim3(32, 8, 4), 256>>>(Wf, Wi, Ws, Wp);
    quant_w2<<<dim3(32, 32, 4), 256>>>(Wf, Wi, Ws, Wp);
    gemm_imma<<<dim3(4096 / BN, 4096 / BM), 256, SMEM_DYN>>>();
    lstm_eltwise_kernel<<<4096, 256>>>(c, bf, bi, bs, bp, out);
}

// round 7
// speedup vs baseline: 3.3209x; 1.0843x over previous
#include <cuda_runtime.h>
#include <math.h>
#include <stdint.h>

// LSTM cell B=4096, IN=H=1024 — int8 Ozaki-split GEMM on IMMA m16n8k32.
//   hx[m,k] ≈ sa_m/16256 · (128·A1 + A2),  W col n: sb_n/16256 · (128·B1 + B2)
//   pre = sa·sb/16256^2 · (16384·A1B1 + 128·(A1B2 + A2B1))   (A2B2 dropped)
// K''=6144: ktiles 0-15 A1·B1, then acc<<=7, 16-31 A2·B1, 32-47 A1·B2.
// R7: 512-thread CTA (16 warps, 32x64 warp tiles) to fix the 2-warp/SMSP
// latency starvation ncu showed (tensor 48% active, occ 12.5%).

#define BM 128
#define BN 256
#define KTILES 48
#define STAGES 3
#define THREADS 512
#define A_STAGE_BYTES (BM * 128)        // 16384
#define B_STAGE_BYTES (BN * 128)        // 32768
#define STAGE_BYTES (A_STAGE_BYTES + B_STAGE_BYTES)
#define SMEM_DYN (STAGES * STAGE_BYTES)

#define SBSCALE (128.0f / (16256.0f * 16256.0f))

static __device__ __align__(16) int8_t g_Aq[4096ull * 4096];  // [m][A1|A2]
static __device__ __align__(16) int8_t g_Bq[4096ull * 4096];  // [n=g*1024+c][B1|B2]
static __device__ float g_sa[4096];          // row max (raw)
static __device__ unsigned g_cmax[4096];     // col max |W| as float bits
static __device__ float g_pre[4ull * 4096ull * 1024ull];

// ---------------- PTX helpers (baseline sm_80 ISA) ----------------
__device__ __forceinline__ uint32_t smem_u32(const void* p) {
    return (uint32_t)__cvta_generic_to_shared(p);
}
__device__ __forceinline__ void cp16(uint32_t dst, const void* src) {
    asm volatile("cp.async.cg.shared.global [%0], [%1], 16;\n" :: "r"(dst), "l"(src));
}
__device__ __forceinline__ void cp_commit() {
    asm volatile("cp.async.commit_group;\n" ::: "memory");
}
#define CP_WAIT(N) asm volatile("cp.async.wait_group %0;\n" :: "n"(N) : "memory")

__device__ __forceinline__ void ldsm_x4(uint32_t* r, uint32_t addr) {
    asm volatile("ldmatrix.sync.aligned.m8n8.x4.shared.b16 {%0,%1,%2,%3}, [%4];\n"
                 : "=r"(r[0]), "=r"(r[1]), "=r"(r[2]), "=r"(r[3]) : "r"(addr));
}
__device__ __forceinline__ void imma16832(int* c, const uint32_t* a,
                                          uint32_t b0, uint32_t b1) {
    asm volatile(
        "mma.sync.aligned.m16n8k32.row.col.s32.s8.s8.s32 "
        "{%0,%1,%2,%3}, {%4,%5,%6,%7}, {%8,%9}, {%0,%1,%2,%3};\n"
        : "+r"(c[0]), "+r"(c[1]), "+r"(c[2]), "+r"(c[3])
        : "r"(a[0]), "r"(a[1]), "r"(a[2]), "r"(a[3]), "r"(b0), "r"(b1));
}

// ---------------- activation quantization ----------------
__global__ __launch_bounds__(256)
void quant_hx(const float* __restrict__ x, const float* __restrict__ h) {
    __shared__ float sred[256];
    const int m = blockIdx.x;
    const int t = threadIdx.x;
    const float* src = (t < 128) ? (x + (size_t)m * 1024 + t * 8)
                                 : (h + (size_t)m * 1024 + (t - 128) * 8);
    float4 v0 = *(const float4*)src;
    float4 v1 = *(const float4*)(src + 4);
    float vals[8] = {v0.x, v0.y, v0.z, v0.w, v1.x, v1.y, v1.z, v1.w};
    float mx = 0.0f;
    #pragma unroll
    for (int j = 0; j < 8; ++j) mx = fmaxf(mx, fabsf(vals[j]));
    sred[t] = mx;
    __syncthreads();
    for (int s = 128; s > 0; s >>= 1) {
        if (t < s) sred[t] = fmaxf(sred[t], sred[t + s]);
        __syncthreads();
    }
    const float sa = fmaxf(sred[0], 1e-30f);
    if (t == 0) g_sa[m] = sa;
    const float inv = 16256.0f / sa;
    char d1[8], d2[8];
    #pragma unroll
    for (int j = 0; j < 8; ++j) {
        int vi = __float2int_rn(vals[j] * inv);
        int b1 = (vi + 64) >> 7;
        int b2 = vi - (b1 << 7);
        d1[j] = (char)b1;
        d2[j] = (char)b2;
    }
    size_t base = (size_t)m * 4096 + t * 8;
    *(uint2*)&g_Aq[base]        = *(uint2*)d1;
    *(uint2*)&g_Aq[base + 2048] = *(uint2*)d2;
}

// ---------------- weight quantization (2-pass, parallel) ----------------
__global__ __launch_bounds__(256)
void colmax_w(const float* __restrict__ Wf, const float* __restrict__ Wi,
              const float* __restrict__ Ws, const float* __restrict__ Wp) {
    __shared__ float red[8][33];
    const int g = blockIdx.z;
    const float* __restrict__ W = (g == 0) ? Wf : (g == 1) ? Wi : (g == 2) ? Ws : Wp;
    const int n0 = blockIdx.x * 32;
    const int k0 = blockIdx.y * 256;
    const int tx = threadIdx.x & 31;
    const int tk = threadIdx.x >> 5;   // 0..7

    float mx = 0.0f;
    #pragma unroll 8
    for (int i = 0; i < 32; ++i) {
        int k = k0 + tk + i * 8;
        mx = fmaxf(mx, fabsf(W[(size_t)k * 1024 + n0 + tx]));
    }
    red[tk][tx] = mx;
    __syncthreads();
    if (tk == 0) {
        float m = red[0][tx];
        #pragma unroll
        for (int j = 1; j < 8; ++j) m = fmaxf(m, red[j][tx]);
        atomicMax((int*)&g_cmax[g * 1024 + n0 + tx], __float_as_int(m));
    }
}

__global__ __launch_bounds__(256)
void quant_w2(const float* __restrict__ Wf, const float* __restrict__ Wi,
              const float* __restrict__ Ws, const float* __restrict__ Wp) {
    __shared__ __align__(8) char t1[32][64];
    __shared__ __align__(8) char t2[32][64];
    const int g = blockIdx.z;
    const float* __restrict__ W = (g == 0) ? Wf : (g == 1) ? Wi : (g == 2) ? Ws : Wp;
    const int n0 = blockIdx.x * 32;
    const int kt = blockIdx.y * 64;
    const int tx = threadIdx.x & 31;
    const int tk = threadIdx.x >> 5;   // 0..7

    const float cm = fmaxf(__int_as_float((int)g_cmax[g * 1024 + n0 + tx]), 1e-30f);
    const float inv = 16256.0f / cm;

    #pragma unroll
    for (int j = 0; j < 8; ++j) {
        int k = kt + tk * 8 + j;
        float v = W[(size_t)k * 1024 + n0 + tx] * inv;
        int vi = __float2int_rn(v);
        int b1 = (vi + 64) >> 7;
        int b2 = vi - (b1 << 7);
        t1[tx][tk * 8 + j] = (char)b1;
        t2[tx][tk * 8 + j] = (char)b2;
    }
    __syncthreads();
    const int r = threadIdx.x >> 3, seg = threadIdx.x & 7;
    size_t row = (size_t)(g * 1024 + n0 + r) * 4096;
    *(uint2*)&g_Bq[row + kt + seg * 8]        = *(uint2*)&t1[r][seg * 8];
    *(uint2*)&g_Bq[row + 2048 + kt + seg * 8] = *(uint2*)&t2[r][seg * 8];
}

// ---------------- IMMA GEMM (16 warps) ----------------
__device__ __forceinline__ void koffs(int kt, int& ka, int& kb) {
    if (kt < 16)      { ka = kt << 7;                 kb = kt << 7; }
    else if (kt < 32) { ka = 2048 + ((kt - 16) << 7); kb = (kt - 16) << 7; }
    else              { ka = (kt - 32) << 7;          kb = 2048 + ((kt - 32) << 7); }
}

__device__ __forceinline__ void load_stage(uint32_t sbase, int stage, int m0, int n0,
                                           int tid) {
    const uint32_t sb = sbase + (uint32_t)(stage % STAGES) * STAGE_BYTES;
    int ka, kb;
    koffs(stage, ka, kb);
    #pragma unroll
    for (int j = 0; j < 2; ++j) {              // A: 128 rows x 128B = 1024 cp16
        int id = j * THREADS + tid;
        int r = id >> 3, c = id & 7;
        uint32_t dst = sb + (uint32_t)(r * 128 + ((c ^ (r & 7)) * 16));
        cp16(dst, g_Aq + ((size_t)(m0 + r) * 4096 + ka + c * 16));
    }
    #pragma unroll
    for (int j = 0; j < 4; ++j) {              // B: 256 rows x 128B = 2048 cp16
        int id = j * THREADS + tid;
        int r = id >> 3, c = id & 7;
        uint32_t dst = sb + (uint32_t)A_STAGE_BYTES
                     + (uint32_t)(r * 128 + ((c ^ (r & 7)) * 16));
        cp16(dst, g_Bq + ((size_t)(n0 + r) * 4096 + kb + c * 16));
    }
}

__global__ __launch_bounds__(THREADS, 1)
void gemm_imma() {
    extern __shared__ char dyn[];
    const uint32_t sbase = smem_u32(dyn);

    const int tid = threadIdx.x;
    const int wid = tid >> 5;
    const int lane = tid & 31;
    const int warp_m = wid & 3;                // 4 slabs x 32 rows
    const int warp_n = wid >> 2;               // 4 slabs x 64 cols
    const int m0 = blockIdx.y * BM;
    const int n0 = blockIdx.x * BN;

    const int lrow = lane & 15;
    const int lhi  = lane >> 4;

    int acc[2][8][4];
    #pragma unroll
    for (int mi = 0; mi < 2; ++mi)
        #pragma unroll
        for (int nj = 0; nj < 8; ++nj)
            #pragma unroll
            for (int q = 0; q < 4; ++q) acc[mi][nj][q] = 0;

    load_stage(sbase, 0, m0, n0, tid); cp_commit();
    load_stage(sbase, 1, m0, n0, tid); cp_commit();

    for (int kt = 0; kt < KTILES; ++kt) {
        CP_WAIT(1);
        __syncthreads();

        if (kt + 2 < KTILES) load_stage(sbase, kt + 2, m0, n0, tid);
        cp_commit();

        if (kt == 16) {                 // acc = 128*G1; continue with cross terms
            #pragma unroll
            for (int mi = 0; mi < 2; ++mi)
                #pragma unroll
                for (int nj = 0; nj < 8; ++nj)
                    #pragma unroll
                    for (int q = 0; q < 4; ++q) acc[mi][nj][q] <<= 7;
        }

        const uint32_t sA = sbase + (uint32_t)(kt % STAGES) * STAGE_BYTES;
        const uint32_t sB = sA + A_STAGE_BYTES;

        #pragma unroll
        for (int ks = 0; ks < 4; ++ks) {       // 4 x k32 per 128B stage
            const int kc = ks * 2 + lhi;       // 16B chunk 0..7
            uint32_t a[2][4];
            #pragma unroll
            for (int mi = 0; mi < 2; ++mi) {
                int r = warp_m * 32 + mi * 16 + lrow;
                uint32_t addr = sA + (uint32_t)(r * 128 + ((kc ^ (r & 7)) * 16));
                ldsm_x4(a[mi], addr);
            }
            #pragma unroll
            for (int nj = 0; nj < 4; ++nj) {
                uint32_t b[4];
                int r = warp_n * 64 + nj * 16 + lrow;
                uint32_t addr = sB + (uint32_t)(r * 128 + ((kc ^ (r & 7)) * 16));
                ldsm_x4(b, addr);
                #pragma unroll
                for (int mi = 0; mi < 2; ++mi) {
                    imma16832(acc[mi][2 * nj],     a[mi], b[0], b[2]);
                    imma16832(acc[mi][2 * nj + 1], a[mi], b[1], b[3]);
                }
            }
        }
    }

    // Epilogue: pre = g_sa[row] * (colmax[n]*SBSCALE) * acc
    const int gid = lane >> 2, tig = lane & 3;
    const int ngb = n0 + warp_n * 64;          // global col 0..4095
    const int gate = ngb >> 10;
    const int col0 = ngb & 1023;
    float* __restrict__ outg = g_pre + (size_t)gate * (4096ull * 1024ull);
    const float* __restrict__ cmf = (const float*)g_cmax;
    #pragma unroll
    for (int mi = 0; mi < 2; ++mi) {
        int row = m0 + warp_m * 32 + mi * 16 + gid;
        float s0 = g_sa[row] * SBSCALE;
        float s1 = g_sa[row + 8] * SBSCALE;
        float* p0 = outg + (size_t)row * 1024 + col0;
        float* p1 = p0 + 8ull * 1024ull;
        #pragma unroll
        for (int nj = 0; nj < 8; ++nj) {
            int col = nj * 8 + tig * 2;
            float2 sb2 = *(const float2*)&cmf[ngb + col];
            *(float2*)(p0 + col) = make_float2(s0 * sb2.x * (float)acc[mi][nj][0],
                                               s0 * sb2.y * (float)acc[mi][nj][1]);
            *(float2*)(p1 + col) = make_float2(s1 * sb2.x * (float)acc[mi][nj][2],
                                               s1 * sb2.y * (float)acc[mi][nj][3]);
        }
    }
}

// ---------------- fused eltwise ----------------
__device__ __forceinline__ float sigf(float z) { return 1.0f / (1.0f + expf(-z)); }

__global__ __launch_bounds__(256)
void lstm_eltwise_kernel(const float* __restrict__ c,
                         const float* __restrict__ bf, const float* __restrict__ bi,
                         const float* __restrict__ bs, const float* __restrict__ bp,
                         float* __restrict__ out) {
    const size_t G = 4096ull * 1024ull;
    const size_t i4 = (size_t)blockIdx.x * blockDim.x + threadIdx.x;
    const size_t idx = i4 * 4;
    const int col = (int)(idx & 1023);

    float4 pf = *(const float4*)&g_pre[idx];
    float4 pi = *(const float4*)&g_pre[G + idx];
    float4 ps = *(const float4*)&g_pre[2 * G + idx];
    float4 pp = *(const float4*)&g_pre[3 * G + idx];
    float4 vbf = *(const float4*)&bf[col];
    float4 vbi = *(const float4*)&bi[col];
    float4 vbs = *(const float4*)&bs[col];
    float4 vbp = *(const float4*)&bp[col];
    float4 vc  = *(const float4*)&c[idx];

    const float* pfv = (const float*)&pf;  const float* piv = (const float*)&pi;
    const float* psv = (const float*)&ps;  const float* ppv = (const float*)&pp;
    const float* bfv = (const float*)&vbf; const float* biv = (const float*)&vbi;
    const float* bsv = (const float*)&vbs; const float* bpv = (const float*)&vbp;
    const float* cv  = (const float*)&vc;

    float4 o; float* ov = (float*)&o;
    #pragma unroll
    for (int j = 0; j < 4; ++j) {
        float f = sigf(pfv[j] + bfv[j]);
        float i = sigf(piv[j] + biv[j]);
        float s = sigf(psv[j] + bsv[j]);
        float p = tanhf(ppv[j] + bpv[j]);
        float cn = cv[j] * f + i * p;
        ov[j] = tanhf(cn) * s;
    }
    *(float4*)&out[idx] = o;
}

// ---------------- launch ----------------
extern "C" void kernel_launch(void* const* d_in, const int* in_sizes, int n_in,
                              void* d_out, int out_size) {
    const float* x  = (const float*)d_in[0];
    const float* h  = (const float*)d_in[1];
    const float* c  = (const float*)d_in[2];
    const float* Wf = (const float*)d_in[3];
    const float* bf = (const float*)d_in[4];
    const float* Wi = (const float*)d_in[5];
    const float* bi = (const float*)d_in[6];
    const float* Ws = (const float*)d_in[7];
    const float* bs = (const float*)d_in[8];
    const float* Wp = (const float*)d_in[9];
    const float* bp = (const float*)d_in[10];
    float* out = (float*)d_out;

    cudaFuncSetAttribute(gemm_imma, cudaFuncAttributeMaxDynamicSharedMemorySize,
                         SMEM_DYN);

    quant_hx<<<4096, 256>>>(x, h);
    colmax_w<<<dim3(32, 8, 4), 256>>>(Wf, Wi, Ws, Wp);
    quant_w2<<<dim3(32, 32, 4), 256>>>(Wf, Wi, Ws, Wp);
    gemm_imma<<<dim3(4096 / BN, 4096 / BM), THREADS, SMEM_DYN>>>();
    lstm_eltwise_kernel<<<4096, 256>>>(c, bf, bi, bs, bp, out);
}

// round 8
// speedup vs baseline: 4.6620x; 1.4038x over previous
#include <cuda_runtime.h>
#include <math.h>
#include <stdint.h>

// LSTM cell B=4096, IN=H=1024 — int8 Karatsuba-Ozaki GEMM on IMMA m16n8k32.
// Quantize: V = round(v * 2031 / scale), V = 17*D1 + D2 (|D1|<=119, |D2|<=8).
// Planes: S1 = D1, S2 = D1 + D2 (|S2| <= 127).
// P1 = S1a*S1b, P2 = S2a*S2b over K=2048 each (16 ktiles per pass).
//   17*(16*P1 + P2) = V*W + 16*D2a*D2b   (dropped term ~2.5e-4 rel)
// acc: pass1 -> acc<<=4 -> pass2.  pre = sa*sb * 17/2031^2 * acc.
// mma.sync dispatch floor is 0.25 instr/cyc/SM, so time ∝ IMMA count:
// 2 passes (32 ktiles) vs 3 (48) => ~238us GEMM vs 357.

#define BM 128
#define BN 256
#define KTILES 32
#define STAGES 3
#define THREADS 512
#define A_STAGE_BYTES (BM * 128)        // 16384
#define B_STAGE_BYTES (BN * 128)        // 32768
#define STAGE_BYTES (A_STAGE_BYTES + B_STAGE_BYTES)
#define SMEM_DYN (STAGES * STAGE_BYTES)

#define VMAXF 2031.0f
#define SBSCALE (17.0f / (VMAXF * VMAXF))

static __device__ __align__(16) int8_t g_Aq[4096ull * 4096];  // [m][S1|S2]
static __device__ __align__(16) int8_t g_Bq[4096ull * 4096];  // [n=g*1024+c][T1|T2]
static __device__ float g_sa[4096];          // row max (raw)
static __device__ unsigned g_cmax[4096];     // col max |W| as float bits
static __device__ float g_pre[4ull * 4096ull * 1024ull];

// ---------------- PTX helpers (baseline sm_80 ISA) ----------------
__device__ __forceinline__ uint32_t smem_u32(const void* p) {
    return (uint32_t)__cvta_generic_to_shared(p);
}
__device__ __forceinline__ void cp16(uint32_t dst, const void* src) {
    asm volatile("cp.async.cg.shared.global [%0], [%1], 16;\n" :: "r"(dst), "l"(src));
}
__device__ __forceinline__ void cp_commit() {
    asm volatile("cp.async.commit_group;\n" ::: "memory");
}
#define CP_WAIT(N) asm volatile("cp.async.wait_group %0;\n" :: "n"(N) : "memory")

__device__ __forceinline__ void ldsm_x4(uint32_t* r, uint32_t addr) {
    asm volatile("ldmatrix.sync.aligned.m8n8.x4.shared.b16 {%0,%1,%2,%3}, [%4];\n"
                 : "=r"(r[0]), "=r"(r[1]), "=r"(r[2]), "=r"(r[3]) : "r"(addr));
}
__device__ __forceinline__ void imma16832(int* c, const uint32_t* a,
                                          uint32_t b0, uint32_t b1) {
    asm volatile(
        "mma.sync.aligned.m16n8k32.row.col.s32.s8.s8.s32 "
        "{%0,%1,%2,%3}, {%4,%5,%6,%7}, {%8,%9}, {%0,%1,%2,%3};\n"
        : "+r"(c[0]), "+r"(c[1]), "+r"(c[2]), "+r"(c[3])
        : "r"(a[0]), "r"(a[1]), "r"(a[2]), "r"(a[3]), "r"(b0), "r"(b1));
}

// Karatsuba digit split: returns S1 = D1, S2 = D1 + D2 for V = 17*D1 + D2.
__device__ __forceinline__ void kdigits(float val, float inv, char& s1, char& s2) {
    int vi = __float2int_rn(val * inv);               // |vi| <= 2031
    int d1 = __float2int_rn((float)vi * (1.0f / 17.0f));  // |d1| <= 119
    int d2 = vi - 17 * d1;                            // |d2| <= 8
    s1 = (char)d1;
    s2 = (char)(d1 + d2);                             // |.| <= 127
}

// ---------------- activation quantization ----------------
__global__ __launch_bounds__(256)
void quant_hx(const float* __restrict__ x, const float* __restrict__ h) {
    __shared__ float sred[256];
    const int m = blockIdx.x;
    const int t = threadIdx.x;
    const float* src = (t < 128) ? (x + (size_t)m * 1024 + t * 8)
                                 : (h + (size_t)m * 1024 + (t - 128) * 8);
    float4 v0 = *(const float4*)src;
    float4 v1 = *(const float4*)(src + 4);
    float vals[8] = {v0.x, v0.y, v0.z, v0.w, v1.x, v1.y, v1.z, v1.w};
    float mx = 0.0f;
    #pragma unroll
    for (int j = 0; j < 8; ++j) mx = fmaxf(mx, fabsf(vals[j]));
    sred[t] = mx;
    __syncthreads();
    for (int s = 128; s > 0; s >>= 1) {
        if (t < s) sred[t] = fmaxf(sred[t], sred[t + s]);
        __syncthreads();
    }
    const float sa = fmaxf(sred[0], 1e-30f);
    if (t == 0) g_sa[m] = sa;
    const float inv = VMAXF / sa;
    char d1[8], d2[8];
    #pragma unroll
    for (int j = 0; j < 8; ++j) kdigits(vals[j], inv, d1[j], d2[j]);
    size_t base = (size_t)m * 4096 + t * 8;
    *(uint2*)&g_Aq[base]        = *(uint2*)d1;   // S1 plane
    *(uint2*)&g_Aq[base + 2048] = *(uint2*)d2;   // S2 plane
}

// ---------------- weight quantization (2-pass, parallel) ----------------
__global__ __launch_bounds__(256)
void colmax_w(const float* __restrict__ Wf, const float* __restrict__ Wi,
              const float* __restrict__ Ws, const float* __restrict__ Wp) {
    __shared__ float red[8][33];
    const int g = blockIdx.z;
    const float* __restrict__ W = (g == 0) ? Wf : (g == 1) ? Wi : (g == 2) ? Ws : Wp;
    const int n0 = blockIdx.x * 32;
    const int k0 = blockIdx.y * 256;
    const int tx = threadIdx.x & 31;
    const int tk = threadIdx.x >> 5;   // 0..7

    float mx = 0.0f;
    #pragma unroll 8
    for (int i = 0; i < 32; ++i) {
        int k = k0 + tk + i * 8;
        mx = fmaxf(mx, fabsf(W[(size_t)k * 1024 + n0 + tx]));
    }
    red[tk][tx] = mx;
    __syncthreads();
    if (tk == 0) {
        float m = red[0][tx];
        #pragma unroll
        for (int j = 1; j < 8; ++j) m = fmaxf(m, red[j][tx]);
        atomicMax((int*)&g_cmax[g * 1024 + n0 + tx], __float_as_int(m));
    }
}

__global__ __launch_bounds__(256)
void quant_w2(const float* __restrict__ Wf, const float* __restrict__ Wi,
              const float* __restrict__ Ws, const float* __restrict__ Wp) {
    __shared__ __align__(8) char t1[32][64];
    __shared__ __align__(8) char t2[32][64];
    const int g = blockIdx.z;
    const float* __restrict__ W = (g == 0) ? Wf : (g == 1) ? Wi : (g == 2) ? Ws : Wp;
    const int n0 = blockIdx.x * 32;
    const int kt = blockIdx.y * 64;
    const int tx = threadIdx.x & 31;
    const int tk = threadIdx.x >> 5;   // 0..7

    const float cm = fmaxf(__int_as_float((int)g_cmax[g * 1024 + n0 + tx]), 1e-30f);
    const float inv = VMAXF / cm;

    #pragma unroll
    for (int j = 0; j < 8; ++j) {
        int k = kt + tk * 8 + j;
        char s1, s2;
        kdigits(W[(size_t)k * 1024 + n0 + tx], inv, s1, s2);
        t1[tx][tk * 8 + j] = s1;
        t2[tx][tk * 8 + j] = s2;
    }
    __syncthreads();
    const int r = threadIdx.x >> 3, seg = threadIdx.x & 7;
    size_t row = (size_t)(g * 1024 + n0 + r) * 4096;
    *(uint2*)&g_Bq[row + kt + seg * 8]        = *(uint2*)&t1[r][seg * 8];
    *(uint2*)&g_Bq[row + 2048 + kt + seg * 8] = *(uint2*)&t2[r][seg * 8];
}

// ---------------- IMMA GEMM (16 warps, 2 Karatsuba passes) ----------------
__device__ __forceinline__ int koff(int kt) {
    return (kt < 16) ? (kt << 7) : (2048 + ((kt - 16) << 7));
}

__device__ __forceinline__ void load_stage(uint32_t sbase, int stage, int m0, int n0,
                                           int tid) {
    const uint32_t sb = sbase + (uint32_t)(stage % STAGES) * STAGE_BYTES;
    const int kk = koff(stage);
    #pragma unroll
    for (int j = 0; j < 2; ++j) {              // A: 128 rows x 128B = 1024 cp16
        int id = j * THREADS + tid;
        int r = id >> 3, c = id & 7;
        uint32_t dst = sb + (uint32_t)(r * 128 + ((c ^ (r & 7)) * 16));
        cp16(dst, g_Aq + ((size_t)(m0 + r) * 4096 + kk + c * 16));
    }
    #pragma unroll
    for (int j = 0; j < 4; ++j) {              // B: 256 rows x 128B = 2048 cp16
        int id = j * THREADS + tid;
        int r = id >> 3, c = id & 7;
        uint32_t dst = sb + (uint32_t)A_STAGE_BYTES
                     + (uint32_t)(r * 128 + ((c ^ (r & 7)) * 16));
        cp16(dst, g_Bq + ((size_t)(n0 + r) * 4096 + kk + c * 16));
    }
}

__global__ __launch_bounds__(THREADS, 1)
void gemm_imma() {
    extern __shared__ char dyn[];
    const uint32_t sbase = smem_u32(dyn);

    const int tid = threadIdx.x;
    const int wid = tid >> 5;
    const int lane = tid & 31;
    const int warp_m = wid & 3;                // 4 slabs x 32 rows
    const int warp_n = wid >> 2;               // 4 slabs x 64 cols
    const int m0 = blockIdx.y * BM;
    const int n0 = blockIdx.x * BN;

    const int lrow = lane & 15;
    const int lhi  = lane >> 4;

    int acc[2][8][4];
    #pragma unroll
    for (int mi = 0; mi < 2; ++mi)
        #pragma unroll
        for (int nj = 0; nj < 8; ++nj)
            #pragma unroll
            for (int q = 0; q < 4; ++q) acc[mi][nj][q] = 0;

    load_stage(sbase, 0, m0, n0, tid); cp_commit();
    load_stage(sbase, 1, m0, n0, tid); cp_commit();

    for (int kt = 0; kt < KTILES; ++kt) {
        CP_WAIT(1);
        __syncthreads();

        if (kt + 2 < KTILES) load_stage(sbase, kt + 2, m0, n0, tid);
        cp_commit();

        if (kt == 16) {                 // acc = 16*P1; continue with P2
            #pragma unroll
            for (int mi = 0; mi < 2; ++mi)
                #pragma unroll
                for (int nj = 0; nj < 8; ++nj)
                    #pragma unroll
                    for (int q = 0; q < 4; ++q) acc[mi][nj][q] <<= 4;
        }

        const uint32_t sA = sbase + (uint32_t)(kt % STAGES) * STAGE_BYTES;
        const uint32_t sB = sA + A_STAGE_BYTES;

        #pragma unroll
        for (int ks = 0; ks < 4; ++ks) {       // 4 x k32 per 128B stage
            const int kc = ks * 2 + lhi;       // 16B chunk 0..7
            uint32_t a[2][4];
            #pragma unroll
            for (int mi = 0; mi < 2; ++mi) {
                int r = warp_m * 32 + mi * 16 + lrow;
                uint32_t addr = sA + (uint32_t)(r * 128 + ((kc ^ (r & 7)) * 16));
                ldsm_x4(a[mi], addr);
            }
            #pragma unroll
            for (int nj = 0; nj < 4; ++nj) {
                uint32_t b[4];
                int r = warp_n * 64 + nj * 16 + lrow;
                uint32_t addr = sB + (uint32_t)(r * 128 + ((kc ^ (r & 7)) * 16));
                ldsm_x4(b, addr);
                #pragma unroll
                for (int mi = 0; mi < 2; ++mi) {
                    imma16832(acc[mi][2 * nj],     a[mi], b[0], b[2]);
                    imma16832(acc[mi][2 * nj + 1], a[mi], b[1], b[3]);
                }
            }
        }
    }

    // Epilogue: pre = g_sa[row] * (colmax[n]*SBSCALE) * acc
    const int gid = lane >> 2, tig = lane & 3;
    const int ngb = n0 + warp_n * 64;          // global col 0..4095
    const int gate = ngb >> 10;
    const int col0 = ngb & 1023;
    float* __restrict__ outg = g_pre + (size_t)gate * (4096ull * 1024ull);
    const float* __restrict__ cmf = (const float*)g_cmax;
    #pragma unroll
    for (int mi = 0; mi < 2; ++mi) {
        int row = m0 + warp_m * 32 + mi * 16 + gid;
        float s0 = g_sa[row] * SBSCALE;
        float s1 = g_sa[row + 8] * SBSCALE;
        float* p0 = outg + (size_t)row * 1024 + col0;
        float* p1 = p0 + 8ull * 1024ull;
        #pragma unroll
        for (int nj = 0; nj < 8; ++nj) {
            int col = nj * 8 + tig * 2;
            float2 sb2 = *(const float2*)&cmf[ngb + col];
            *(float2*)(p0 + col) = make_float2(s0 * sb2.x * (float)acc[mi][nj][0],
                                               s0 * sb2.y * (float)acc[mi][nj][1]);
            *(float2*)(p1 + col) = make_float2(s1 * sb2.x * (float)acc[mi][nj][2],
                                               s1 * sb2.y * (float)acc[mi][nj][3]);
        }
    }
}

// ---------------- fused eltwise ----------------
__device__ __forceinline__ float sigf(float z) { return 1.0f / (1.0f + expf(-z)); }

__global__ __launch_bounds__(256)
void lstm_eltwise_kernel(const float* __restrict__ c,
                         const float* __restrict__ bf, const float* __restrict__ bi,
                         const float* __restrict__ bs, const float* __restrict__ bp,
                         float* __restrict__ out) {
    const size_t G = 4096ull * 1024ull;
    const size_t i4 = (size_t)blockIdx.x * blockDim.x + threadIdx.x;
    const size_t idx = i4 * 4;
    const int col = (int)(idx & 1023);

    float4 pf = *(const float4*)&g_pre[idx];
    float4 pi = *(const float4*)&g_pre[G + idx];
    float4 ps = *(const float4*)&g_pre[2 * G + idx];
    float4 pp = *(const float4*)&g_pre[3 * G + idx];
    float4 vbf = *(const float4*)&bf[col];
    float4 vbi = *(const float4*)&bi[col];
    float4 vbs = *(const float4*)&bs[col];
    float4 vbp = *(const float4*)&bp[col];
    float4 vc  = *(const float4*)&c[idx];

    const float* pfv = (const float*)&pf;  const float* piv = (const float*)&pi;
    const float* psv = (const float*)&ps;  const float* ppv = (const float*)&pp;
    const float* bfv = (const float*)&vbf; const float* biv = (const float*)&vbi;
    const float* bsv = (const float*)&vbs; const float* bpv = (const float*)&vbp;
    const float* cv  = (const float*)&vc;

    float4 o; float* ov = (float*)&o;
    #pragma unroll
    for (int j = 0; j < 4; ++j) {
        float f = sigf(pfv[j] + bfv[j]);
        float i = sigf(piv[j] + biv[j]);
        float s = sigf(psv[j] + bsv[j]);
        float p = tanhf(ppv[j] + bpv[j]);
        float cn = cv[j] * f + i * p;
        ov[j] = tanhf(cn) * s;
    }
    *(float4*)&out[idx] = o;
}

// ---------------- launch ----------------
extern "C" void kernel_launch(void* const* d_in, const int* in_sizes, int n_in,
                              void* d_out, int out_size) {
    const float* x  = (const float*)d_in[0];
    const float* h  = (const float*)d_in[1];
    const float* c  = (const float*)d_in[2];
    const float* Wf = (const float*)d_in[3];
    const float* bf = (const float*)d_in[4];
    const float* Wi = (const float*)d_in[5];
    const float* bi = (const float*)d_in[6];
    const float* Ws = (const float*)d_in[7];
    const float* bs = (const float*)d_in[8];
    const float* Wp = (const float*)d_in[9];
    const float* bp = (const float*)d_in[10];
    float* out = (float*)d_out;

    cudaFuncSetAttribute(gemm_imma, cudaFuncAttributeMaxDynamicSharedMemorySize,
                         SMEM_DYN);

    quant_hx<<<4096, 256>>>(x, h);
    colmax_w<<<dim3(32, 8, 4), 256>>>(Wf, Wi, Ws, Wp);
    quant_w2<<<dim3(32, 32, 4), 256>>>(Wf, Wi, Ws, Wp);
    gemm_imma<<<dim3(4096 / BN, 4096 / BM), THREADS, SMEM_DYN>>>();
    lstm_eltwise_kernel<<<4096, 256>>>(c, bf, bi, bs, bp, out);
}

// round 9
// speedup vs baseline: 4.7228x; 1.0130x over previous
#include <cuda_runtime.h>
#include <math.h>
#include <stdint.h>

// LSTM cell B=4096, IN=H=1024 — int8 Karatsuba-Ozaki GEMM on IMMA m16n8k32,
// with the LSTM eltwise fused into the GEMM epilogue.
// Quantize: V = round(v * 2031 / scale), V = 17*D1 + D2 (|D1|<=119, |D2|<=8).
// Planes: S1 = D1, S2 = D1 + D2 (|S2| <= 127).
//   17*(16*P1 + P2) = V*W + 16*D2a*D2b   (dropped term ~2.5e-4 rel)
// GEMM tile: M=128 x N=256 where the 256 N-columns are the SAME 64 output
// columns of ALL FOUR gates (smem B row r <-> gate r>>6, col col0+(r&63)).
// Epilogue: stage pre-activations in smem, apply bias+sigmoid/tanh+cell
// update, write h_new directly. No g_pre scratch, no separate eltwise kernel.

#define BM 128
#define BN 256
#define KTILES 32
#define STAGES 3
#define THREADS 512
#define A_STAGE_BYTES (BM * 128)        // 16384
#define B_STAGE_BYTES (BN * 128)        // 32768
#define STAGE_BYTES (A_STAGE_BYTES + B_STAGE_BYTES)
#define SMEM_DYN (STAGES * STAGE_BYTES) // 147456; epilogue reuses 133120
#define PSTRIDE 260                     // floats per staged row (64*4 + pad)

#define VMAXF 2031.0f
#define SBSCALE (17.0f / (VMAXF * VMAXF))

static __device__ __align__(16) int8_t g_Aq[4096ull * 4096];  // [m][S1|S2]
static __device__ __align__(16) int8_t g_Bq[4096ull * 4096];  // [n=g*1024+c][T1|T2]
static __device__ float g_sa[4096];          // row max (raw)
static __device__ unsigned g_cmax[4096];     // col max |W| as float bits

// ---------------- PTX helpers (baseline sm_80 ISA) ----------------
__device__ __forceinline__ uint32_t smem_u32(const void* p) {
    return (uint32_t)__cvta_generic_to_shared(p);
}
__device__ __forceinline__ void cp16(uint32_t dst, const void* src) {
    asm volatile("cp.async.cg.shared.global [%0], [%1], 16;\n" :: "r"(dst), "l"(src));
}
__device__ __forceinline__ void cp_commit() {
    asm volatile("cp.async.commit_group;\n" ::: "memory");
}
#define CP_WAIT(N) asm volatile("cp.async.wait_group %0;\n" :: "n"(N) : "memory")

__device__ __forceinline__ void ldsm_x4(uint32_t* r, uint32_t addr) {
    asm volatile("ldmatrix.sync.aligned.m8n8.x4.shared.b16 {%0,%1,%2,%3}, [%4];\n"
                 : "=r"(r[0]), "=r"(r[1]), "=r"(r[2]), "=r"(r[3]) : "r"(addr));
}
__device__ __forceinline__ void imma16832(int* c, const uint32_t* a,
                                          uint32_t b0, uint32_t b1) {
    asm volatile(
        "mma.sync.aligned.m16n8k32.row.col.s32.s8.s8.s32 "
        "{%0,%1,%2,%3}, {%4,%5,%6,%7}, {%8,%9}, {%0,%1,%2,%3};\n"
        : "+r"(c[0]), "+r"(c[1]), "+r"(c[2]), "+r"(c[3])
        : "r"(a[0]), "r"(a[1]), "r"(a[2]), "r"(a[3]), "r"(b0), "r"(b1));
}

// Karatsuba digit split: S1 = D1, S2 = D1 + D2 for V = 17*D1 + D2.
__device__ __forceinline__ void kdigits(float val, float inv, char& s1, char& s2) {
    int vi = __float2int_rn(val * inv);                   // |vi| <= 2031
    int d1 = __float2int_rn((float)vi * (1.0f / 17.0f));  // |d1| <= 119
    int d2 = vi - 17 * d1;                                // |d2| <= 8
    s1 = (char)d1;
    s2 = (char)(d1 + d2);                                 // |.| <= 127
}

// ---------------- activation quantization ----------------
__global__ __launch_bounds__(256)
void quant_hx(const float* __restrict__ x, const float* __restrict__ h) {
    __shared__ float sred[256];
    const int m = blockIdx.x;
    const int t = threadIdx.x;
    const float* src = (t < 128) ? (x + (size_t)m * 1024 + t * 8)
                                 : (h + (size_t)m * 1024 + (t - 128) * 8);
    float4 v0 = *(const float4*)src;
    float4 v1 = *(const float4*)(src + 4);
    float vals[8] = {v0.x, v0.y, v0.z, v0.w, v1.x, v1.y, v1.z, v1.w};
    float mx = 0.0f;
    #pragma unroll
    for (int j = 0; j < 8; ++j) mx = fmaxf(mx, fabsf(vals[j]));
    sred[t] = mx;
    __syncthreads();
    for (int s = 128; s > 0; s >>= 1) {
        if (t < s) sred[t] = fmaxf(sred[t], sred[t + s]);
        __syncthreads();
    }
    const float sa = fmaxf(sred[0], 1e-30f);
    if (t == 0) g_sa[m] = sa;
    const float inv = VMAXF / sa;
    char d1[8], d2[8];
    #pragma unroll
    for (int j = 0; j < 8; ++j) kdigits(vals[j], inv, d1[j], d2[j]);
    size_t base = (size_t)m * 4096 + t * 8;
    *(uint2*)&g_Aq[base]        = *(uint2*)d1;   // S1 plane
    *(uint2*)&g_Aq[base + 2048] = *(uint2*)d2;   // S2 plane
}

// ---------------- weight quantization (2-pass, parallel) ----------------
__global__ __launch_bounds__(256)
void colmax_w(const float* __restrict__ Wf, const float* __restrict__ Wi,
              const float* __restrict__ Ws, const float* __restrict__ Wp) {
    __shared__ float red[8][33];
    const int g = blockIdx.z;
    const float* __restrict__ W = (g == 0) ? Wf : (g == 1) ? Wi : (g == 2) ? Ws : Wp;
    const int n0 = blockIdx.x * 32;
    const int k0 = blockIdx.y * 256;
    const int tx = threadIdx.x & 31;
    const int tk = threadIdx.x >> 5;   // 0..7

    float mx = 0.0f;
    #pragma unroll 8
    for (int i = 0; i < 32; ++i) {
        int k = k0 + tk + i * 8;
        mx = fmaxf(mx, fabsf(W[(size_t)k * 1024 + n0 + tx]));
    }
    red[tk][tx] = mx;
    __syncthreads();
    if (tk == 0) {
        float m = red[0][tx];
        #pragma unroll
        for (int j = 1; j < 8; ++j) m = fmaxf(m, red[j][tx]);
        atomicMax((int*)&g_cmax[g * 1024 + n0 + tx], __float_as_int(m));
    }
}

__global__ __launch_bounds__(256)
void quant_w2(const float* __restrict__ Wf, const float* __restrict__ Wi,
              const float* __restrict__ Ws, const float* __restrict__ Wp) {
    __shared__ __align__(8) char t1[32][64];
    __shared__ __align__(8) char t2[32][64];
    const int g = blockIdx.z;
    const float* __restrict__ W = (g == 0) ? Wf : (g == 1) ? Wi : (g == 2) ? Ws : Wp;
    const int n0 = blockIdx.x * 32;
    const int kt = blockIdx.y * 64;
    const int tx = threadIdx.x & 31;
    const int tk = threadIdx.x >> 5;   // 0..7

    const float cm = fmaxf(__int_as_float((int)g_cmax[g * 1024 + n0 + tx]), 1e-30f);
    const float inv = VMAXF / cm;

    #pragma unroll
    for (int j = 0; j < 8; ++j) {
        int k = kt + tk * 8 + j;
        char s1, s2;
        kdigits(W[(size_t)k * 1024 + n0 + tx], inv, s1, s2);
        t1[tx][tk * 8 + j] = s1;
        t2[tx][tk * 8 + j] = s2;
    }
    __syncthreads();
    const int r = threadIdx.x >> 3, seg = threadIdx.x & 7;
    size_t row = (size_t)(g * 1024 + n0 + r) * 4096;
    *(uint2*)&g_Bq[row + kt + seg * 8]        = *(uint2*)&t1[r][seg * 8];
    *(uint2*)&g_Bq[row + 2048 + kt + seg * 8] = *(uint2*)&t2[r][seg * 8];
}

// ---------------- fused IMMA GEMM + LSTM eltwise ----------------
__device__ __forceinline__ int koff(int kt) {
    return (kt < 16) ? (kt << 7) : (2048 + ((kt - 16) << 7));
}

__device__ __forceinline__ void load_stage(uint32_t sbase, int stage, int m0,
                                           int col0, int tid) {
    const uint32_t sb = sbase + (uint32_t)(stage % STAGES) * STAGE_BYTES;
    const int kk = koff(stage);
    #pragma unroll
    for (int j = 0; j < 2; ++j) {              // A: 128 rows x 128B = 1024 cp16
        int id = j * THREADS + tid;
        int r = id >> 3, c = id & 7;
        uint32_t dst = sb + (uint32_t)(r * 128 + ((c ^ (r & 7)) * 16));
        cp16(dst, g_Aq + ((size_t)(m0 + r) * 4096 + kk + c * 16));
    }
    #pragma unroll
    for (int j = 0; j < 4; ++j) {              // B: 256 rows x 128B = 2048 cp16
        int id = j * THREADS + tid;
        int r = id >> 3, c = id & 7;
        // smem row r <-> global B row: gate (r>>6), column col0 + (r&63)
        int nrow = ((r >> 6) << 10) + col0 + (r & 63);
        uint32_t dst = sb + (uint32_t)A_STAGE_BYTES
                     + (uint32_t)(r * 128 + ((c ^ (r & 7)) * 16));
        cp16(dst, g_Bq + ((size_t)nrow * 4096 + kk + c * 16));
    }
}

__device__ __forceinline__ float sigf(float z) { return 1.0f / (1.0f + expf(-z)); }

__global__ __launch_bounds__(THREADS, 1)
void gemm_fused(const float* __restrict__ cin,
                const float* __restrict__ bf, const float* __restrict__ bi,
                const float* __restrict__ bs, const float* __restrict__ bp,
                float* __restrict__ out) {
    extern __shared__ char dyn[];
    const uint32_t sbase = smem_u32(dyn);

    const int tid = threadIdx.x;
    const int wid = tid >> 5;
    const int lane = tid & 31;
    const int warp_m = wid & 3;                // 4 slabs x 32 rows
    const int warp_n = wid >> 2;               // == gate 0..3 (64-col slab)
    const int m0 = blockIdx.y * BM;
    const int col0 = blockIdx.x * 64;          // output columns col0..col0+63

    const int lrow = lane & 15;
    const int lhi  = lane >> 4;

    int acc[2][8][4];
    #pragma unroll
    for (int mi = 0; mi < 2; ++mi)
        #pragma unroll
        for (int nj = 0; nj < 8; ++nj)
            #pragma unroll
            for (int q = 0; q < 4; ++q) acc[mi][nj][q] = 0;

    load_stage(sbase, 0, m0, col0, tid); cp_commit();
    load_stage(sbase, 1, m0, col0, tid); cp_commit();

    for (int kt = 0; kt < KTILES; ++kt) {
        CP_WAIT(1);
        __syncthreads();

        if (kt + 2 < KTILES) load_stage(sbase, kt + 2, m0, col0, tid);
        cp_commit();

        if (kt == 16) {                 // acc = 16*P1; continue with P2
            #pragma unroll
            for (int mi = 0; mi < 2; ++mi)
                #pragma unroll
                for (int nj = 0; nj < 8; ++nj)
                    #pragma unroll
                    for (int q = 0; q < 4; ++q) acc[mi][nj][q] <<= 4;
        }

        const uint32_t sA = sbase + (uint32_t)(kt % STAGES) * STAGE_BYTES;
        const uint32_t sB = sA + A_STAGE_BYTES;

        #pragma unroll
        for (int ks = 0; ks < 4; ++ks) {       // 4 x k32 per 128B stage
            const int kc = ks * 2 + lhi;       // 16B chunk 0..7
            uint32_t a[2][4];
            #pragma unroll
            for (int mi = 0; mi < 2; ++mi) {
                int r = warp_m * 32 + mi * 16 + lrow;
                uint32_t addr = sA + (uint32_t)(r * 128 + ((kc ^ (r & 7)) * 16));
                ldsm_x4(a[mi], addr);
            }
            #pragma unroll
            for (int nj = 0; nj < 4; ++nj) {
                uint32_t b[4];
                int r = warp_n * 64 + nj * 16 + lrow;
                uint32_t addr = sB + (uint32_t)(r * 128 + ((kc ^ (r & 7)) * 16));
                ldsm_x4(b, addr);
                #pragma unroll
                for (int mi = 0; mi < 2; ++mi) {
                    imma16832(acc[mi][2 * nj],     a[mi], b[0], b[2]);
                    imma16832(acc[mi][2 * nj + 1], a[mi], b[1], b[3]);
                }
            }
        }
    }

    // ---- epilogue phase 1: stage scaled pre-activations in smem ----
    __syncthreads();                           // all ldsm done; reuse pipeline smem
    float* __restrict__ pre_s = (float*)dyn;   // [128][PSTRIDE], gcol = gate*64+col
    const float* __restrict__ cmf = (const float*)g_cmax;
    {
        const int gid = lane >> 2, tig = lane & 3;
        #pragma unroll
        for (int mi = 0; mi < 2; ++mi) {
            int r0 = warp_m * 32 + mi * 16 + gid;
            float s0 = g_sa[m0 + r0] * SBSCALE;
            float s1 = g_sa[m0 + r0 + 8] * SBSCALE;
            #pragma unroll
            for (int nj = 0; nj < 8; ++nj) {
                int cl = nj * 8 + tig * 2;                 // 0..62 within gate slab
                float2 cm2 = *(const float2*)&cmf[warp_n * 1024 + col0 + cl];
                int gcol = warp_n * 64 + cl;
                *(float2*)&pre_s[r0 * PSTRIDE + gcol] =
                    make_float2(s0 * cm2.x * (float)acc[mi][nj][0],
                                s0 * cm2.y * (float)acc[mi][nj][1]);
                *(float2*)&pre_s[(r0 + 8) * PSTRIDE + gcol] =
                    make_float2(s1 * cm2.x * (float)acc[mi][nj][2],
                                s1 * cm2.y * (float)acc[mi][nj][3]);
            }
        }
    }
    __syncthreads();

    // ---- epilogue phase 2: LSTM eltwise, write h_new ----
    {
        const int c4 = (tid & 15) * 4;         // column group 0..60
        float4 vbf = *(const float4*)&bf[col0 + c4];
        float4 vbi = *(const float4*)&bi[col0 + c4];
        float4 vbs = *(const float4*)&bs[col0 + c4];
        float4 vbp = *(const float4*)&bp[col0 + c4];
        const float* bfv = (const float*)&vbf;
        const float* biv = (const float*)&vbi;
        const float* bsv = (const float*)&vbs;
        const float* bpv = (const float*)&vbp;

        #pragma unroll
        for (int pass = 0; pass < 4; ++pass) {
            int rowl = (tid >> 4) + pass * 32;         // 0..127
            const float* rowp = pre_s + rowl * PSTRIDE;
            float4 pf = *(const float4*)&rowp[c4];
            float4 pi = *(const float4*)&rowp[64 + c4];
            float4 ps = *(const float4*)&rowp[128 + c4];
            float4 pp = *(const float4*)&rowp[192 + c4];
            float4 vc = *(const float4*)&cin[(size_t)(m0 + rowl) * 1024 + col0 + c4];

            const float* pfv = (const float*)&pf;
            const float* piv = (const float*)&pi;
            const float* psv = (const float*)&ps;
            const float* ppv = (const float*)&pp;
            const float* cv  = (const float*)&vc;

            float4 o; float* ov = (float*)&o;
            #pragma unroll
            for (int j = 0; j < 4; ++j) {
                float f = sigf(pfv[j] + bfv[j]);
                float i = sigf(piv[j] + biv[j]);
                float s = sigf(psv[j] + bsv[j]);
                float p = tanhf(ppv[j] + bpv[j]);
                float cn = cv[j] * f + i * p;
                ov[j] = tanhf(cn) * s;
            }
            *(float4*)&out[(size_t)(m0 + rowl) * 1024 + col0 + c4] = o;
        }
    }
}

// ---------------- launch ----------------
extern "C" void kernel_launch(void* const* d_in, const int* in_sizes, int n_in,
                              void* d_out, int out_size) {
    const float* x  = (const float*)d_in[0];
    const float* h  = (const float*)d_in[1];
    const float* c  = (const float*)d_in[2];
    const float* Wf = (const float*)d_in[3];
    const float* bf = (const float*)d_in[4];
    const float* Wi = (const float*)d_in[5];
    const float* bi = (const float*)d_in[6];
    const float* Ws = (const float*)d_in[7];
    const float* bs = (const float*)d_in[8];
    const float* Wp = (const float*)d_in[9];
    const float* bp = (const float*)d_in[10];
    float* out = (float*)d_out;

    cudaFuncSetAttribute(gemm_fused, cudaFuncAttributeMaxDynamicSharedMemorySize,
                         SMEM_DYN);

    quant_hx<<<4096, 256>>>(x, h);
    colmax_w<<<dim3(32, 8, 4), 256>>>(Wf, Wi, Ws, Wp);
    quant_w2<<<dim3(32, 32, 4), 256>>>(Wf, Wi, Ws, Wp);
    gemm_fused<<<dim3(16, 32), THREADS, SMEM_DYN>>>(c, bf, bi, bs, bp, out);
}

// round 11
// speedup vs baseline: 5.6531x; 1.1970x over previous
#include <cuda_runtime.h>
#include <math.h>
#include <stdint.h>

// LSTM cell B=4096, IN=H=1024 — int8 Karatsuba-Ozaki GEMM on IMMA m16n8k32,
// LSTM eltwise fused into the epilogue, 2 CTAs/SM so epilogues overlap
// co-resident mainloops (tensor-dispatch floor is the only GEMM cost).
// Quantize: V = round(v * 2031 / scale), V = 17*D1 + D2 (|D1|<=119, |D2|<=8).
// Planes: S1 = D1, S2 = D1 + D2 (|S2| <= 127).
//   17*(16*P1 + P2) = V*W + 16*D2a*D2b   (dropped term ~2.5e-4 rel)
// GEMM tile: M=128 x N=128, N = same 32 output columns of all 4 gates
// (smem B row r <-> gate r>>5, col col0+(r&31)).

#define BM 128
#define BN 128
#define KTILES 32
#define STAGES 3
#define THREADS 256
#define A_STAGE_BYTES (BM * 128)        // 16384
#define B_STAGE_BYTES (BN * 128)        // 16384
#define STAGE_BYTES (A_STAGE_BYTES + B_STAGE_BYTES)   // 32768
#define SMEM_DYN (STAGES * STAGE_BYTES)               // 98304
#define PSTRIDE 132                     // floats per staged row (128 + pad)

#define VMAXF 2031.0f
#define SBSCALE (17.0f / (VMAXF * VMAXF))

static __device__ __align__(16) int8_t g_Aq[4096ull * 4096];  // [m][S1|S2]
static __device__ __align__(16) int8_t g_Bq[4096ull * 4096];  // [n=g*1024+c][T1|T2]
static __device__ float g_sa[4096];          // row max (raw)
static __device__ unsigned g_cmax[4096];     // col max |W| as float bits

// ---------------- PTX helpers (baseline sm_80 ISA) ----------------
__device__ __forceinline__ uint32_t smem_u32(const void* p) {
    return (uint32_t)__cvta_generic_to_shared(p);
}
__device__ __forceinline__ void cp16(uint32_t dst, const void* src) {
    asm volatile("cp.async.cg.shared.global [%0], [%1], 16;\n" :: "r"(dst), "l"(src));
}
__device__ __forceinline__ void cp_commit() {
    asm volatile("cp.async.commit_group;\n" ::: "memory");
}
#define CP_WAIT(N) asm volatile("cp.async.wait_group %0;\n" :: "n"(N) : "memory")

__device__ __forceinline__ void ldsm_x4(uint32_t* r, uint32_t addr) {
    asm volatile("ldmatrix.sync.aligned.m8n8.x4.shared.b16 {%0,%1,%2,%3}, [%4];\n"
                 : "=r"(r[0]), "=r"(r[1]), "=r"(r[2]), "=r"(r[3]) : "r"(addr));
}
__device__ __forceinline__ void imma16832(int* c, const uint32_t* a,
                                          uint32_t b0, uint32_t b1) {
    asm volatile(
        "mma.sync.aligned.m16n8k32.row.col.s32.s8.s8.s32 "
        "{%0,%1,%2,%3}, {%4,%5,%6,%7}, {%8,%9}, {%0,%1,%2,%3};\n"
        : "+r"(c[0]), "+r"(c[1]), "+r"(c[2]), "+r"(c[3])
        : "r"(a[0]), "r"(a[1]), "r"(a[2]), "r"(a[3]), "r"(b0), "r"(b1));
}

// Karatsuba digit split: S1 = D1, S2 = D1 + D2 for V = 17*D1 + D2.
__device__ __forceinline__ void kdigits(float val, float inv, char& s1, char& s2) {
    int vi = __float2int_rn(val * inv);                   // |vi| <= 2031
    int d1 = __float2int_rn((float)vi * (1.0f / 17.0f));  // |d1| <= 119
    int d2 = vi - 17 * d1;                                // |d2| <= 8
    s1 = (char)d1;
    s2 = (char)(d1 + d2);                                 // |.| <= 127
}

// Fast activations: __expf/__fdividef are MUFU-based, rel err ~1e-6 —
// negligible vs the 4.7e-4 quantization error.
__device__ __forceinline__ float sigf(float z) {
    return __fdividef(1.0f, 1.0f + __expf(-z));
}
__device__ __forceinline__ float tanhfast(float z) {
    // tanh(z) = 2*sigmoid(2z) - 1
    return __fdividef(2.0f, 1.0f + __expf(-2.0f * z)) - 1.0f;
}

// ---------------- activation quantization ----------------
__global__ __launch_bounds__(256)
void quant_hx(const float* __restrict__ x, const float* __restrict__ h) {
    __shared__ float sred[256];
    const int m = blockIdx.x;
    const int t = threadIdx.x;
    const float* src = (t < 128) ? (x + (size_t)m * 1024 + t * 8)
                                 : (h + (size_t)m * 1024 + (t - 128) * 8);
    float4 v0 = *(const float4*)src;
    float4 v1 = *(const float4*)(src + 4);
    float vals[8] = {v0.x, v0.y, v0.z, v0.w, v1.x, v1.y, v1.z, v1.w};
    float mx = 0.0f;
    #pragma unroll
    for (int j = 0; j < 8; ++j) mx = fmaxf(mx, fabsf(vals[j]));
    sred[t] = mx;
    __syncthreads();
    for (int s = 128; s > 0; s >>= 1) {
        if (t < s) sred[t] = fmaxf(sred[t], sred[t + s]);
        __syncthreads();
    }
    const float sa = fmaxf(sred[0], 1e-30f);
    if (t == 0) g_sa[m] = sa;
    const float inv = VMAXF / sa;
    char d1[8], d2[8];
    #pragma unroll
    for (int j = 0; j < 8; ++j) kdigits(vals[j], inv, d1[j], d2[j]);
    size_t base = (size_t)m * 4096 + t * 8;
    *(uint2*)&g_Aq[base]        = *(uint2*)d1;   // S1 plane
    *(uint2*)&g_Aq[base + 2048] = *(uint2*)d2;   // S2 plane
}

// ---------------- weight quantization (2-pass, parallel) ----------------
__global__ __launch_bounds__(256)
void colmax_w(const float* __restrict__ Wf, const float* __restrict__ Wi,
              const float* __restrict__ Ws, const float* __restrict__ Wp) {
    __shared__ float red[8][33];
    const int g = blockIdx.z;
    const float* __restrict__ W = (g == 0) ? Wf : (g == 1) ? Wi : (g == 2) ? Ws : Wp;
    const int n0 = blockIdx.x * 32;
    const int k0 = blockIdx.y * 256;
    const int tx = threadIdx.x & 31;
    const int tk = threadIdx.x >> 5;   // 0..7

    float mx = 0.0f;
    #pragma unroll 8
    for (int i = 0; i < 32; ++i) {
        int k = k0 + tk + i * 8;
        mx = fmaxf(mx, fabsf(W[(size_t)k * 1024 + n0 + tx]));
    }
    red[tk][tx] = mx;
    __syncthreads();
    if (tk == 0) {
        float m = red[0][tx];
        #pragma unroll
        for (int j = 1; j < 8; ++j) m = fmaxf(m, red[j][tx]);
        atomicMax((int*)&g_cmax[g * 1024 + n0 + tx], __float_as_int(m));
    }
}

__global__ __launch_bounds__(256)
void quant_w2(const float* __restrict__ Wf, const float* __restrict__ Wi,
              const float* __restrict__ Ws, const float* __restrict__ Wp) {
    __shared__ __align__(8) char t1[32][64];
    __shared__ __align__(8) char t2[32][64];
    const int g = blockIdx.z;
    const float* __restrict__ W = (g == 0) ? Wf : (g == 1) ? Wi : (g == 2) ? Ws : Wp;
    const int n0 = blockIdx.x * 32;
    const int kt = blockIdx.y * 64;
    const int tx = threadIdx.x & 31;
    const int tk = threadIdx.x >> 5;   // 0..7

    const float cm = fmaxf(__int_as_float((int)g_cmax[g * 1024 + n0 + tx]), 1e-30f);
    const float inv = VMAXF / cm;

    #pragma unroll
    for (int j = 0; j < 8; ++j) {
        int k = kt + tk * 8 + j;
        char s1, s2;
        kdigits(W[(size_t)k * 1024 + n0 + tx], inv, s1, s2);
        t1[tx][tk * 8 + j] = s1;
        t2[tx][tk * 8 + j] = s2;
    }
    __syncthreads();
    const int r = threadIdx.x >> 3, seg = threadIdx.x & 7;
    size_t row = (size_t)(g * 1024 + n0 + r) * 4096;
    *(uint2*)&g_Bq[row + kt + seg * 8]        = *(uint2*)&t1[r][seg * 8];
    *(uint2*)&g_Bq[row + 2048 + kt + seg * 8] = *(uint2*)&t2[r][seg * 8];
}

// ---------------- fused IMMA GEMM + LSTM eltwise ----------------
__device__ __forceinline__ int koff(int kt) {
    return (kt < 16) ? (kt << 7) : (2048 + ((kt - 16) << 7));
}

__device__ __forceinline__ void load_stage(uint32_t sbase, int stage, int m0,
                                           int col0, int tid) {
    const uint32_t sb = sbase + (uint32_t)(stage % STAGES) * STAGE_BYTES;
    const int kk = koff(stage);
    #pragma unroll
    for (int j = 0; j < 4; ++j) {              // A: 128 rows x 128B = 1024 cp16
        int id = j * THREADS + tid;
        int r = id >> 3, c = id & 7;
        uint32_t dst = sb + (uint32_t)(r * 128 + ((c ^ (r & 7)) * 16));
        cp16(dst, g_Aq + ((size_t)(m0 + r) * 4096 + kk + c * 16));
    }
    #pragma unroll
    for (int j = 0; j < 4; ++j) {              // B: 128 rows x 128B = 1024 cp16
        int id = j * THREADS + tid;
        int r = id >> 3, c = id & 7;
        // smem row r <-> global B row: gate (r>>5), column col0 + (r&31)
        int nrow = ((r >> 5) << 10) + col0 + (r & 31);
        uint32_t dst = sb + (uint32_t)A_STAGE_BYTES
                     + (uint32_t)(r * 128 + ((c ^ (r & 7)) * 16));
        cp16(dst, g_Bq + ((size_t)nrow * 4096 + kk + c * 16));
    }
}

__global__ __launch_bounds__(THREADS, 2)
void gemm_fused(const float* __restrict__ cin,
                const float* __restrict__ bf, const float* __restrict__ bi,
                const float* __restrict__ bs, const float* __restrict__ bp,
                float* __restrict__ out) {
    extern __shared__ char dyn[];
    const uint32_t sbase = smem_u32(dyn);

    const int tid = threadIdx.x;
    const int wid = tid >> 5;
    const int lane = tid & 31;
    const int warp_m = wid & 3;                // 4 slabs x 32 rows
    const int warp_n = wid >> 2;               // 0..1, 64-col slab
    const int m0 = blockIdx.y * BM;
    const int col0 = blockIdx.x * 32;          // output columns col0..col0+31

    const int lrow = lane & 15;
    const int lhi  = lane >> 4;

    int acc[2][8][4];
    #pragma unroll
    for (int mi = 0; mi < 2; ++mi)
        #pragma unroll
        for (int nj = 0; nj < 8; ++nj)
            #pragma unroll
            for (int q = 0; q < 4; ++q) acc[mi][nj][q] = 0;

    load_stage(sbase, 0, m0, col0, tid); cp_commit();
    load_stage(sbase, 1, m0, col0, tid); cp_commit();

    for (int kt = 0; kt < KTILES; ++kt) {
        CP_WAIT(1);
        __syncthreads();

        if (kt + 2 < KTILES) load_stage(sbase, kt + 2, m0, col0, tid);
        cp_commit();

        if (kt == 16) {                 // acc = 16*P1; continue with P2
            #pragma unroll
            for (int mi = 0; mi < 2; ++mi)
                #pragma unroll
                for (int nj = 0; nj < 8; ++nj)
                    #pragma unroll
                    for (int q = 0; q < 4; ++q) acc[mi][nj][q] <<= 4;
        }

        const uint32_t sA = sbase + (uint32_t)(kt % STAGES) * STAGE_BYTES;
        const uint32_t sB = sA + A_STAGE_BYTES;

        #pragma unroll
        for (int ks = 0; ks < 4; ++ks) {       // 4 x k32 per 128B stage
            const int kc = ks * 2 + lhi;       // 16B chunk 0..7
            uint32_t a[2][4];
            #pragma unroll
            for (int mi = 0; mi < 2; ++mi) {
                int r = warp_m * 32 + mi * 16 + lrow;
                uint32_t addr = sA + (uint32_t)(r * 128 + ((kc ^ (r & 7)) * 16));
                ldsm_x4(a[mi], addr);
            }
            #pragma unroll
            for (int nj = 0; nj < 4; ++nj) {
                uint32_t b[4];
                int r = warp_n * 64 + nj * 16 + lrow;
                uint32_t addr = sB + (uint32_t)(r * 128 + ((kc ^ (r & 7)) * 16));
                ldsm_x4(b, addr);
                #pragma unroll
                for (int mi = 0; mi < 2; ++mi) {
                    imma16832(acc[mi][2 * nj],     a[mi], b[0], b[2]);
                    imma16832(acc[mi][2 * nj + 1], a[mi], b[1], b[3]);
                }
            }
        }
    }

    // ---- epilogue phase 1: stage scaled pre-activations in smem ----
    // gcol == smem-B row rn (0..127): gate = rn>>5, col-in-gate = rn&31.
    __syncthreads();                           // all ldsm done; reuse pipeline smem
    float* __restrict__ pre_s = (float*)dyn;   // [128][PSTRIDE]
    const float* __restrict__ cmf = (const float*)g_cmax;
    {
        const int gid = lane >> 2, tig = lane & 3;
        #pragma unroll
        for (int mi = 0; mi < 2; ++mi) {
            int r0 = warp_m * 32 + mi * 16 + gid;
            float s0 = g_sa[m0 + r0] * SBSCALE;
            float s1 = g_sa[m0 + r0 + 8] * SBSCALE;
            #pragma unroll
            for (int nj = 0; nj < 8; ++nj) {
                int rn = warp_n * 64 + (nj >> 1) * 16 + (nj & 1) * 8 + tig * 2;
                float2 cm2;
                cm2.x = cmf[((rn >> 5) << 10) + col0 + (rn & 31)];
                cm2.y = cmf[(((rn + 1) >> 5) << 10) + col0 + ((rn + 1) & 31)];
                *(float2*)&pre_s[r0 * PSTRIDE + rn] =
                    make_float2(s0 * cm2.x * (float)acc[mi][nj][0],
                                s0 * cm2.y * (float)acc[mi][nj][1]);
                *(float2*)&pre_s[(r0 + 8) * PSTRIDE + rn] =
                    make_float2(s1 * cm2.x * (float)acc[mi][nj][2],
                                s1 * cm2.y * (float)acc[mi][nj][3]);
            }
        }
    }
    __syncthreads();

    // ---- epilogue phase 2: LSTM eltwise, write h_new ----
    {
        const int c4 = (tid & 7) * 4;          // column group 0..28
        float4 vbf = *(const float4*)&bf[col0 + c4];
        float4 vbi = *(const float4*)&bi[col0 + c4];
        float4 vbs = *(const float4*)&bs[col0 + c4];
        float4 vbp = *(const float4*)&bp[col0 + c4];
        const float* bfv = (const float*)&vbf;
        const float* biv = (const float*)&vbi;
        const float* bsv = (const float*)&vbs;
        const float* bpv = (const float*)&vbp;

        #pragma unroll
        for (int pass = 0; pass < 4; ++pass) {
            int rowl = (tid >> 3) + pass * 32;         // 0..127
            const float* rowp = pre_s + rowl * PSTRIDE;
            float4 pf = *(const float4*)&rowp[c4];          // gate 0 (forget)
            float4 pi = *(const float4*)&rowp[32 + c4];     // gate 1 (ignore)
            float4 ps = *(const float4*)&rowp[64 + c4];     // gate 2 (select)
            float4 pp = *(const float4*)&rowp[96 + c4];     // gate 3 (predict)
            float4 vc = *(const float4*)&cin[(size_t)(m0 + rowl) * 1024 + col0 + c4];

            const float* pfv = (const float*)&pf;
            const float* piv = (const float*)&pi;
            const float* psv = (const float*)&ps;
            const float* ppv = (const float*)&pp;
            const float* cv  = (const float*)&vc;

            float4 o; float* ov = (float*)&o;
            #pragma unroll
            for (int j = 0; j < 4; ++j) {
                float f = sigf(pfv[j] + bfv[j]);
                float i = sigf(piv[j] + biv[j]);
                float s = sigf(psv[j] + bsv[j]);
                float p = tanhfast(ppv[j] + bpv[j]);
                float cn = cv[j] * f + i * p;
                ov[j] = tanhfast(cn) * s;
            }
            *(float4*)&out[(size_t)(m0 + rowl) * 1024 + col0 + c4] = o;
        }
    }
}

// ---------------- launch ----------------
extern "C" void kernel_launch(void* const* d_in, const int* in_sizes, int n_in,
                              void* d_out, int out_size) {
    const float* x  = (const float*)d_in[0];
    const float* h  = (const float*)d_in[1];
    const float* c  = (const float*)d_in[2];
    const float* Wf = (const float*)d_in[3];
    const float* bf = (const float*)d_in[4];
    const float* Wi = (const float*)d_in[5];
    const float* bi = (const float*)d_in[6];
    const float* Ws = (const float*)d_in[7];
    const float* bs = (const float*)d_in[8];
    const float* Wp = (const float*)d_in[9];
    const float* bp = (const float*)d_in[10];
    float* out = (float*)d_out;

    cudaFuncSetAttribute(gemm_fused, cudaFuncAttributeMaxDynamicSharedMemorySize,
                         SMEM_DYN);

    quant_hx<<<4096, 256>>>(x, h);
    colmax_w<<<dim3(32, 8, 4), 256>>>(Wf, Wi, Ws, Wp);
    quant_w2<<<dim3(32, 32, 4), 256>>>(Wf, Wi, Ws, Wp);
    gemm_fused<<<dim3(32, 32), THREADS, SMEM_DYN>>>(c, bf, bi, bs, bp, out);
}